// round 2
// baseline (speedup 1.0000x reference)
#include <cuda_runtime.h>
#include <cstddef>
#include <math.h>

// ---------------- problem constants ----------------
#define TKN     2048            // B*S
#define BATCH   2
#define SEQ     1024
#define DIM     512
#define NH      8
#define DHD     64
#define NLAYER  12
#define NEXP    8
#define FFD     2048
#define VOC     32000
#define MAXTILES 24             // sum_e ceil(cnt_e/128) <= 2048/128 + 8 = 24
#define MAXROWS  (MAXTILES*128) // 3072

// output layout: [logits (B*S*V)] [aux (1)] [rlogits (L*B*S*E)]
#define LOGITS_N ((size_t)BATCH*SEQ*VOC)
#define AUX_OFF  LOGITS_N
#define RL_OFF   (LOGITS_N + 1)

// ---------------- scratch (device globals; no runtime alloc) ----------------
__device__ float g_x[TKN*DIM];
__device__ float g_h[TKN*DIM];
__device__ float g_qkv[TKN*3*DIM];
__device__ float g_P[(size_t)BATCH*NH*SEQ*SEQ];      // 64 MB attention probs
__device__ float g_o[TKN*DIM];
__device__ float g_hid[(size_t)MAXROWS*FFD];         // sorted expert hidden
__device__ float g_pe[TKN*NEXP];                     // router probs per token
__device__ int   g_topi[TKN];
__device__ float g_topw[TKN];
__device__ int   g_cnt[NEXP];
__device__ float g_sp[NEXP];
__device__ int   g_padoff[NEXP];
__device__ int   g_cursor[NEXP];
__device__ int   g_tileexp[MAXTILES];
__device__ int   g_perm[MAXROWS];
__device__ float g_aux[1];

// ---------------- helpers ----------------
__device__ __forceinline__ float gelu_exact(float x) {
    return 0.5f * x * (1.0f + erff(x * 0.70710678118654752f));
}

__device__ __forceinline__ float block_reduce_sum(float v) {
    __shared__ float sb[33];
    __syncthreads();
    int lane = threadIdx.x & 31, wid = threadIdx.x >> 5;
    #pragma unroll
    for (int o = 16; o > 0; o >>= 1) v += __shfl_down_sync(0xffffffffu, v, o);
    if (lane == 0) sb[wid] = v;
    __syncthreads();
    if (threadIdx.x == 0) {
        float s = 0.f;
        int nw = blockDim.x >> 5;
        for (int i = 0; i < nw; i++) s += sb[i];
        sb[32] = s;
    }
    __syncthreads();
    return sb[32];
}

__device__ __forceinline__ float block_reduce_max(float v) {
    __shared__ float sm[33];
    __syncthreads();
    int lane = threadIdx.x & 31, wid = threadIdx.x >> 5;
    #pragma unroll
    for (int o = 16; o > 0; o >>= 1) v = fmaxf(v, __shfl_down_sync(0xffffffffu, v, o));
    if (lane == 0) sm[wid] = v;
    __syncthreads();
    if (threadIdx.x == 0) {
        float s = -1e30f;
        int nw = blockDim.x >> 5;
        for (int i = 0; i < nw; i++) s = fmaxf(s, sm[i]);
        sm[32] = s;
    }
    __syncthreads();
    return sm[32];
}

// ---------------- embedding ----------------
__global__ __launch_bounds__(128) void embed_kernel(
    const int* __restrict__ ids, const float* __restrict__ tok,
    const float* __restrict__ pos)
{
    int t = blockIdx.x;
    int tid = threadIdx.x;                 // 128 threads, one float4 each (512 f)
    if (t == 0 && tid == 0) g_aux[0] = 0.f;
    int id = ids[t];
    int s  = t & (SEQ - 1);
    float4 a = ((const float4*)(tok + (size_t)id * DIM))[tid];
    float4 b = ((const float4*)(pos + (size_t)s  * DIM))[tid];
    float4 o; o.x = a.x + b.x; o.y = a.y + b.y; o.z = a.z + b.z; o.w = a.w + b.w;
    ((float4*)(g_x + (size_t)t * DIM))[tid] = o;
}

// ---------------- rmsnorm ----------------
__global__ __launch_bounds__(128) void rmsnorm_kernel(
    const float* __restrict__ X, const float* __restrict__ w, float* __restrict__ Y)
{
    int t = blockIdx.x;
    int tid = threadIdx.x;
    float4 v = ((const float4*)(X + (size_t)t * DIM))[tid];
    float ss = v.x*v.x + v.y*v.y + v.z*v.z + v.w*v.w;
    ss = block_reduce_sum(ss);
    float scale = rsqrtf(ss * (1.0f / DIM) + 1e-6f);
    float4 wv = ((const float4*)w)[tid];
    float4 o;
    o.x = v.x * scale * wv.x;
    o.y = v.y * scale * wv.y;
    o.z = v.z * scale * wv.z;
    o.w = v.w * scale * wv.w;
    ((float4*)(Y + (size_t)t * DIM))[tid] = o;
}

// ---------------- generic SGEMM 128x128x16, 256 thr, 8x8 microtile ------------
// MODE 0: C = acc + bias            (bias may be null)
// MODE 1: C += acc + bias           (residual into C)
// MODE 2: expert GEMM1: A rows gathered via rowmap (pad rows -> zeros),
//         B/bias selected by tileexp[by], C[gm] = gelu(acc + bias)
// MODE 3: expert GEMM2: A direct, B/bias by tileexp[by],
//         C[rowmap[gm]] += topw * (acc + bias)  (skip pad rows)
template <int MODE>
__global__ void __launch_bounds__(256) sgemm_k(
    int N, int K,
    const float* __restrict__ A,
    const float* __restrict__ B,
    const float* __restrict__ bias,
    float* __restrict__ C,
    const int* __restrict__ rowmap,
    const int* __restrict__ tileexp,
    long bStride, long biasStride,
    const float* __restrict__ topw)
{
    const int bx = blockIdx.x;   // N tile
    const int by = blockIdx.y;   // M tile
    if (MODE == 2 || MODE == 3) {
        int e = tileexp[by];
        if (e < 0) return;
        B    += (long)e * bStride;
        bias += (long)e * biasStride;
    }
    __shared__ float As[16][128];
    __shared__ float Bs[16][128];
    const int tid  = threadIdx.x;
    const int arow = tid >> 2;            // 0..63
    const int acol = (tid & 3) << 2;      // 0,4,8,12
    const int brow = tid >> 5;            // 0..7
    const int bcol = (tid & 31) << 2;     // 0..124

    const float* ap0; const float* ap1;
    {
        int r0 = by * 128 + arow;
        int r1 = r0 + 64;
        if (MODE == 2) {
            int t0 = rowmap[r0];
            int t1 = rowmap[r1];
            ap0 = (t0 >= 0) ? A + (long)t0 * K : nullptr;
            ap1 = (t1 >= 0) ? A + (long)t1 * K : nullptr;
        } else {
            ap0 = A + (long)r0 * K;
            ap1 = A + (long)r1 * K;
        }
    }
    const float* bp = B + (long)bx * 128 + bcol;

    float acc[8][8];
    #pragma unroll
    for (int i = 0; i < 8; i++)
        #pragma unroll
        for (int j = 0; j < 8; j++) acc[i][j] = 0.f;

    const int tr = (tid >> 4) << 3;
    const int tc = (tid & 15) << 3;

    for (int k0 = 0; k0 < K; k0 += 16) {
        float4 a0 = ap0 ? *(const float4*)(ap0 + k0 + acol) : make_float4(0.f,0.f,0.f,0.f);
        float4 a1 = ap1 ? *(const float4*)(ap1 + k0 + acol) : make_float4(0.f,0.f,0.f,0.f);
        As[acol+0][arow]    = a0.x;
        As[acol+1][arow]    = a0.y;
        As[acol+2][arow]    = a0.z;
        As[acol+3][arow]    = a0.w;
        As[acol+0][arow+64] = a1.x;
        As[acol+1][arow+64] = a1.y;
        As[acol+2][arow+64] = a1.z;
        As[acol+3][arow+64] = a1.w;
        float4 b0 = *(const float4*)(bp + (long)(k0 + brow)     * N);
        float4 b1 = *(const float4*)(bp + (long)(k0 + brow + 8) * N);
        *(float4*)&Bs[brow][bcol]     = b0;
        *(float4*)&Bs[brow + 8][bcol] = b1;
        __syncthreads();
        #pragma unroll
        for (int k = 0; k < 16; k++) {
            float4 m0 = *(const float4*)&As[k][tr];
            float4 m1 = *(const float4*)&As[k][tr + 4];
            float4 n0 = *(const float4*)&Bs[k][tc];
            float4 n1 = *(const float4*)&Bs[k][tc + 4];
            float rm[8] = {m0.x, m0.y, m0.z, m0.w, m1.x, m1.y, m1.z, m1.w};
            float rn[8] = {n0.x, n0.y, n0.z, n0.w, n1.x, n1.y, n1.z, n1.w};
            #pragma unroll
            for (int i = 0; i < 8; i++)
                #pragma unroll
                for (int j = 0; j < 8; j++)
                    acc[i][j] += rm[i] * rn[j];
        }
        __syncthreads();
    }

    #pragma unroll
    for (int i = 0; i < 8; i++) {
        int gm = by * 128 + tr + i;
        int gn = bx * 128 + tc;
        if (MODE == 0) {
            float* cp = C + (long)gm * N + gn;
            #pragma unroll
            for (int j = 0; j < 8; j++)
                cp[j] = acc[i][j] + (bias ? bias[gn + j] : 0.f);
        } else if (MODE == 1) {
            float* cp = C + (long)gm * N + gn;
            #pragma unroll
            for (int j = 0; j < 8; j++)
                cp[j] = cp[j] + acc[i][j] + bias[gn + j];
        } else if (MODE == 2) {
            float* cp = C + (long)gm * N + gn;
            #pragma unroll
            for (int j = 0; j < 8; j++)
                cp[j] = gelu_exact(acc[i][j] + bias[gn + j]);
        } else {
            int t = rowmap[gm];
            if (t >= 0) {
                float w = topw[t];
                float* cp = C + (long)t * N + gn;
                #pragma unroll
                for (int j = 0; j < 8; j++)
                    cp[j] += w * (acc[i][j] + bias[gn + j]);
            }
        }
    }
}

// ---------------- attention: scores + causal softmax -> P ----------------
__global__ __launch_bounds__(256) void attn_scores_kernel()
{
    int q  = blockIdx.x & (SEQ - 1);
    int bh = blockIdx.x >> 10;
    int b  = bh >> 3, h = bh & 7;
    __shared__ float qv[DHD];
    __shared__ float sc[SEQ];
    const float* qrow = g_qkv + ((size_t)(b * SEQ + q)) * 1536 + h * DHD;
    if (threadIdx.x < DHD) qv[threadIdx.x] = qrow[threadIdx.x];
    __syncthreads();
    int nk = q + 1;
    float lmax = -1e30f;
    for (int k = threadIdx.x; k < nk; k += blockDim.x) {
        const float* krow = g_qkv + ((size_t)(b * SEQ + k)) * 1536 + DIM + h * DHD;
        float dot = 0.f;
        #pragma unroll
        for (int d = 0; d < DHD; d += 4) {
            float4 kv = *(const float4*)(krow + d);
            dot += qv[d] * kv.x + qv[d+1] * kv.y + qv[d+2] * kv.z + qv[d+3] * kv.w;
        }
        float s = dot * 0.125f;     // 1/sqrt(64)
        sc[k] = s;
        lmax = fmaxf(lmax, s);
    }
    float m = block_reduce_max(lmax);
    float lsum = 0.f;
    for (int k = threadIdx.x; k < nk; k += blockDim.x) {
        float e = expf(sc[k] - m);
        sc[k] = e;
        lsum += e;
    }
    float ssum = block_reduce_sum(lsum);
    float inv = 1.0f / ssum;
    float* prow = g_P + ((size_t)bh * SEQ + q) * SEQ;
    for (int k = threadIdx.x; k < SEQ; k += blockDim.x)
        prow[k] = (k < nk) ? sc[k] * inv : 0.f;
}

// ---------------- attention: O = P @ V (causal-limited) ----------------
__global__ __launch_bounds__(256) void attn_pv_kernel()
{
    int qt = blockIdx.x;    // 0..15 query tile of 64
    int bh = blockIdx.y;    // 0..15
    int b = bh >> 3, h = bh & 7;
    const int tid = threadIdx.x;
    __shared__ float Ps[32][64];
    __shared__ float Vs[32][64];
    const float* Pbase = g_P + ((size_t)bh * SEQ + qt * 64) * SEQ;
    const float* Vbase = g_qkv + (size_t)b * SEQ * 1536 + 2 * DIM + h * DHD;
    const int arow = tid >> 3;          // 0..31  q-local
    const int acol = (tid & 7) << 2;    // 0..28  k offset
    const int brow = tid >> 4;          // 0..15  k-row
    const int bcol = (tid & 15) << 2;   // 0..60  d
    const int tr = (tid >> 4) << 2;
    const int tc = (tid & 15) << 2;
    float acc[4][4];
    #pragma unroll
    for (int i = 0; i < 4; i++)
        #pragma unroll
        for (int j = 0; j < 4; j++) acc[i][j] = 0.f;
    int kmax = (qt + 1) * 64;
    for (int k0 = 0; k0 < kmax; k0 += 32) {
        float4 a0 = *(const float4*)(Pbase + (size_t)arow * SEQ + k0 + acol);
        float4 a1 = *(const float4*)(Pbase + (size_t)(arow + 32) * SEQ + k0 + acol);
        Ps[acol+0][arow]    = a0.x;
        Ps[acol+1][arow]    = a0.y;
        Ps[acol+2][arow]    = a0.z;
        Ps[acol+3][arow]    = a0.w;
        Ps[acol+0][arow+32] = a1.x;
        Ps[acol+1][arow+32] = a1.y;
        Ps[acol+2][arow+32] = a1.z;
        Ps[acol+3][arow+32] = a1.w;
        float4 v0 = *(const float4*)(Vbase + (size_t)(k0 + brow)      * 1536 + bcol);
        float4 v1 = *(const float4*)(Vbase + (size_t)(k0 + brow + 16) * 1536 + bcol);
        *(float4*)&Vs[brow][bcol]      = v0;
        *(float4*)&Vs[brow + 16][bcol] = v1;
        __syncthreads();
        #pragma unroll
        for (int k = 0; k < 32; k++) {
            float4 rm = *(const float4*)&Ps[k][tr];
            float4 rn = *(const float4*)&Vs[k][tc];
            float m[4] = {rm.x, rm.y, rm.z, rm.w};
            float n[4] = {rn.x, rn.y, rn.z, rn.w};
            #pragma unroll
            for (int i = 0; i < 4; i++)
                #pragma unroll
                for (int j = 0; j < 4; j++)
                    acc[i][j] += m[i] * n[j];
        }
        __syncthreads();
    }
    #pragma unroll
    for (int i = 0; i < 4; i++) {
        int q = qt * 64 + tr + i;
        float* op = g_o + ((size_t)(b * SEQ + q)) * DIM + h * DHD + tc;
        #pragma unroll
        for (int j = 0; j < 4; j++) op[j] = acc[i][j];
    }
}

// ---------------- router ----------------
__global__ __launch_bounds__(32) void zero_router_kernel()
{
    if (threadIdx.x < NEXP) g_cnt[threadIdx.x] = 0;
}

__global__ __launch_bounds__(128) void router_kernel(
    const float* __restrict__ rW, const float* __restrict__ rb,
    float* __restrict__ rl_out)
{
    int t = blockIdx.x;
    int tid = threadIdx.x;
    float acc[NEXP];
    #pragma unroll
    for (int e = 0; e < NEXP; e++) acc[e] = 0.f;
    for (int k = tid; k < DIM; k += 128) {
        float hv = g_h[(size_t)t * DIM + k];
        const float* r = rW + (size_t)k * NEXP;
        float4 r0 = *(const float4*)(r);
        float4 r1 = *(const float4*)(r + 4);
        acc[0] += hv * r0.x; acc[1] += hv * r0.y; acc[2] += hv * r0.z; acc[3] += hv * r0.w;
        acc[4] += hv * r1.x; acc[5] += hv * r1.y; acc[6] += hv * r1.z; acc[7] += hv * r1.w;
    }
    __shared__ float red[4][NEXP];
    int lane = tid & 31, w = tid >> 5;
    #pragma unroll
    for (int e = 0; e < NEXP; e++)
        #pragma unroll
        for (int o = 16; o > 0; o >>= 1)
            acc[e] += __shfl_down_sync(0xffffffffu, acc[e], o);
    if (lane == 0)
        #pragma unroll
        for (int e = 0; e < NEXP; e++) red[w][e] = acc[e];
    __syncthreads();
    if (tid == 0) {
        float rl[NEXP], p[NEXP];
        #pragma unroll
        for (int e = 0; e < NEXP; e++)
            rl[e] = red[0][e] + red[1][e] + red[2][e] + red[3][e] + rb[e];
        #pragma unroll
        for (int e = 0; e < NEXP; e++) rl_out[(size_t)t * NEXP + e] = rl[e];
        float m = rl[0];
        #pragma unroll
        for (int e = 1; e < NEXP; e++) m = fmaxf(m, rl[e]);
        float s = 0.f;
        #pragma unroll
        for (int e = 0; e < NEXP; e++) { p[e] = expf(rl[e] - m); s += p[e]; }
        float inv = 1.0f / s;
        float best = -1.f; int bi = 0;
        #pragma unroll
        for (int e = 0; e < NEXP; e++) {
            p[e] *= inv;
            g_pe[(size_t)t * NEXP + e] = p[e];
            if (p[e] > best) { best = p[e]; bi = e; }
        }
        g_topi[t] = bi;
        g_topw[t] = best;
        atomicAdd(&g_cnt[bi], 1);
    }
}

// deterministic per-expert prob sums (fixed reduction tree, no float atomics)
__global__ __launch_bounds__(256) void expert_sum_kernel()
{
    int e = blockIdx.x;
    float s = 0.f;
    for (int t = threadIdx.x; t < TKN; t += blockDim.x)
        s += g_pe[(size_t)t * NEXP + e];
    s = block_reduce_sum(s);
    if (threadIdx.x == 0) g_sp[e] = s;
}

__global__ __launch_bounds__(128) void moe_setup_kernel()
{
    int tid = threadIdx.x;
    for (int i = tid; i < MAXROWS; i += blockDim.x) g_perm[i] = -1;
    if (tid < NEXP) g_cursor[tid] = 0;
    __syncthreads();
    if (tid == 0) {
        int off = 0, tile = 0;
        float aux = 0.f;
        for (int e = 0; e < NEXP; e++) {
            g_padoff[e] = off;
            int c = g_cnt[e];
            aux += (float)c * g_sp[e];
            int nt = (c + 127) >> 7;
            for (int k = 0; k < nt; k++) g_tileexp[tile++] = e;
            off += nt << 7;
        }
        for (; tile < MAXTILES; tile++) g_tileexp[tile] = -1;
        g_aux[0] += (float)NEXP * aux / ((float)TKN * (float)TKN);
    }
}

__global__ __launch_bounds__(128) void scatter_kernel()
{
    int t = blockIdx.x * blockDim.x + threadIdx.x;
    if (t >= TKN) return;
    int e = g_topi[t];
    int pos = atomicAdd(&g_cursor[e], 1);
    g_perm[g_padoff[e] + pos] = t;
}

__global__ void write_aux_kernel(float* __restrict__ out)
{
    out[0] = g_aux[0];
}

// ---------------- launch ----------------
extern "C" void kernel_launch(void* const* d_in, const int* in_sizes, int n_in,
                              void* d_out, int out_size)
{
    const int*   ids  = (const int*)  d_in[0];
    const float* tok  = (const float*)d_in[1];
    const float* pos  = (const float*)d_in[2];
    const float* Wqkv = (const float*)d_in[3];
    const float* bqkv = (const float*)d_in[4];
    const float* Wo   = (const float*)d_in[5];
    const float* bo   = (const float*)d_in[6];
    const float* rW   = (const float*)d_in[7];
    const float* rb   = (const float*)d_in[8];
    const float* eW1  = (const float*)d_in[9];
    const float* eb1  = (const float*)d_in[10];
    const float* eW2  = (const float*)d_in[11];
    const float* eb2  = (const float*)d_in[12];
    const float* n1w  = (const float*)d_in[13];
    const float* n2w  = (const float*)d_in[14];
    const float* noww = (const float*)d_in[15];
    const float* lmW  = (const float*)d_in[16];
    float* out = (float*)d_out;

    void *px, *ph, *pqkv, *po, *phid, *pperm, *ptile, *ptopw;
    cudaGetSymbolAddress(&px,   g_x);
    cudaGetSymbolAddress(&ph,   g_h);
    cudaGetSymbolAddress(&pqkv, g_qkv);
    cudaGetSymbolAddress(&po,   g_o);
    cudaGetSymbolAddress(&phid, g_hid);
    cudaGetSymbolAddress(&pperm, g_perm);
    cudaGetSymbolAddress(&ptile, g_tileexp);
    cudaGetSymbolAddress(&ptopw, g_topw);
    float* x   = (float*)px;
    float* h   = (float*)ph;
    float* qkv = (float*)pqkv;
    float* o   = (float*)po;
    float* hid = (float*)phid;

    embed_kernel<<<TKN, 128>>>(ids, tok, pos);

    for (int l = 0; l < NLAYER; l++) {
        // attention block
        rmsnorm_kernel<<<TKN, 128>>>(x, n1w + (size_t)l * DIM, h);
        sgemm_k<0><<<dim3(12, 16), 256>>>(3 * DIM, DIM,
            h, Wqkv + (size_t)l * DIM * 3 * DIM, bqkv + (size_t)l * 3 * DIM,
            qkv, nullptr, nullptr, 0, 0, nullptr);
        attn_scores_kernel<<<BATCH * NH * SEQ, 256>>>();
        attn_pv_kernel<<<dim3(16, BATCH * NH), 256>>>();
        sgemm_k<1><<<dim3(4, 16), 256>>>(DIM, DIM,
            o, Wo + (size_t)l * DIM * DIM, bo + (size_t)l * DIM,
            x, nullptr, nullptr, 0, 0, nullptr);

        // MoE block
        rmsnorm_kernel<<<TKN, 128>>>(x, n2w + (size_t)l * DIM, h);
        zero_router_kernel<<<1, 32>>>();
        router_kernel<<<TKN, 128>>>(rW + (size_t)l * DIM * NEXP,
                                    rb + (size_t)l * NEXP,
                                    out + RL_OFF + (size_t)l * TKN * NEXP);
        expert_sum_kernel<<<NEXP, 256>>>();
        moe_setup_kernel<<<1, 128>>>();
        scatter_kernel<<<16, 128>>>();

        sgemm_k<2><<<dim3(16, MAXTILES), 256>>>(FFD, DIM,
            h, eW1 + (size_t)l * NEXP * DIM * FFD, eb1 + (size_t)l * NEXP * FFD,
            hid, (const int*)pperm, (const int*)ptile,
            (long)DIM * FFD, (long)FFD, nullptr);
        sgemm_k<3><<<dim3(4, MAXTILES), 256>>>(DIM, FFD,
            hid, eW2 + (size_t)l * NEXP * FFD * DIM, eb2 + (size_t)l * NEXP * DIM,
            x, (const int*)pperm, (const int*)ptile,
            (long)FFD * DIM, (long)DIM, (const float*)ptopw);
    }

    // final norm + LM head
    rmsnorm_kernel<<<TKN, 128>>>(x, noww, h);
    sgemm_k<0><<<dim3(VOC / 128, 16), 256>>>(VOC, DIM,
        h, lmW, nullptr, out, nullptr, nullptr, 0, 0, nullptr);
    write_aux_kernel<<<1, 1>>>(out + AUX_OFF);
}

// round 3
// speedup vs baseline: 1.4478x; 1.4478x over previous
#include <cuda_runtime.h>
#include <cstddef>
#include <math.h>

// ---------------- problem constants ----------------
#define TKN     2048            // B*S
#define BATCH   2
#define SEQ     1024
#define DIM     512
#define NH      8
#define DHD     64
#define NLAYER  12
#define NEXP    8
#define FFD     2048
#define VOC     32000
#define MAXTILES 24             // sum_e ceil(cnt_e/128) <= 2048/128 + 8 = 24
#define MAXROWS  (MAXTILES*128) // 3072

// output layout: [logits (B*S*V)] [aux (1)] [rlogits (L*B*S*E)]
#define LOGITS_N ((size_t)BATCH*SEQ*VOC)
#define AUX_OFF  LOGITS_N
#define RL_OFF   (LOGITS_N + 1)

// ---------------- scratch (device globals; no runtime alloc) ----------------
__device__ float g_x[TKN*DIM];
__device__ float g_h[TKN*DIM];
__device__ float g_qkv[TKN*3*DIM];
__device__ float g_o[TKN*DIM];
__device__ float g_hid[(size_t)MAXROWS*FFD];         // sorted expert hidden
__device__ float g_pe[TKN*NEXP];                     // router probs per token
__device__ int   g_topi[TKN];
__device__ float g_topw[TKN];
__device__ int   g_cnt[NEXP];
__device__ float g_sp[NEXP];
__device__ int   g_padoff[NEXP];
__device__ int   g_cursor[NEXP];
__device__ int   g_tileexp[MAXTILES];
__device__ int   g_perm[MAXROWS];
__device__ float g_aux[1];

// ---------------- helpers ----------------
__device__ __forceinline__ float gelu_exact(float x) {
    return 0.5f * x * (1.0f + erff(x * 0.70710678118654752f));
}

__device__ __forceinline__ float block_reduce_sum(float v) {
    __shared__ float sb[33];
    __syncthreads();
    int lane = threadIdx.x & 31, wid = threadIdx.x >> 5;
    #pragma unroll
    for (int o = 16; o > 0; o >>= 1) v += __shfl_down_sync(0xffffffffu, v, o);
    if (lane == 0) sb[wid] = v;
    __syncthreads();
    if (threadIdx.x == 0) {
        float s = 0.f;
        int nw = blockDim.x >> 5;
        for (int i = 0; i < nw; i++) s += sb[i];
        sb[32] = s;
    }
    __syncthreads();
    return sb[32];
}

// ---------------- embedding ----------------
__global__ __launch_bounds__(128) void embed_kernel(
    const int* __restrict__ ids, const float* __restrict__ tok,
    const float* __restrict__ pos)
{
    int t = blockIdx.x;
    int tid = threadIdx.x;                 // 128 threads, one float4 each (512 f)
    if (t == 0 && tid == 0) g_aux[0] = 0.f;
    int id = ids[t];
    int s  = t & (SEQ - 1);
    float4 a = ((const float4*)(tok + (size_t)id * DIM))[tid];
    float4 b = ((const float4*)(pos + (size_t)s  * DIM))[tid];
    float4 o; o.x = a.x + b.x; o.y = a.y + b.y; o.z = a.z + b.z; o.w = a.w + b.w;
    ((float4*)(g_x + (size_t)t * DIM))[tid] = o;
}

// ---------------- rmsnorm ----------------
__global__ __launch_bounds__(128) void rmsnorm_kernel(
    const float* __restrict__ X, const float* __restrict__ w, float* __restrict__ Y)
{
    int t = blockIdx.x;
    int tid = threadIdx.x;
    float4 v = ((const float4*)(X + (size_t)t * DIM))[tid];
    float ss = v.x*v.x + v.y*v.y + v.z*v.z + v.w*v.w;
    ss = block_reduce_sum(ss);
    float scale = rsqrtf(ss * (1.0f / DIM) + 1e-6f);
    float4 wv = ((const float4*)w)[tid];
    float4 o;
    o.x = v.x * scale * wv.x;
    o.y = v.y * scale * wv.y;
    o.z = v.z * scale * wv.z;
    o.w = v.w * scale * wv.w;
    ((float4*)(Y + (size_t)t * DIM))[tid] = o;
}

// ---------------- generic SGEMM 128x128x16, 256 thr, 8x8 microtile ------------
template <int MODE>
__global__ void __launch_bounds__(256) sgemm_k(
    int N, int K,
    const float* __restrict__ A,
    const float* __restrict__ B,
    const float* __restrict__ bias,
    float* __restrict__ C,
    const int* __restrict__ rowmap,
    const int* __restrict__ tileexp,
    long bStride, long biasStride,
    const float* __restrict__ topw)
{
    const int bx = blockIdx.x;   // N tile
    const int by = blockIdx.y;   // M tile
    if (MODE == 2 || MODE == 3) {
        int e = tileexp[by];
        if (e < 0) return;
        B    += (long)e * bStride;
        bias += (long)e * biasStride;
    }
    __shared__ float As[16][128];
    __shared__ float Bs[16][128];
    const int tid  = threadIdx.x;
    const int arow = tid >> 2;            // 0..63
    const int acol = (tid & 3) << 2;      // 0,4,8,12
    const int brow = tid >> 5;            // 0..7
    const int bcol = (tid & 31) << 2;     // 0..124

    const float* ap0; const float* ap1;
    {
        int r0 = by * 128 + arow;
        int r1 = r0 + 64;
        if (MODE == 2) {
            int t0 = rowmap[r0];
            int t1 = rowmap[r1];
            ap0 = (t0 >= 0) ? A + (long)t0 * K : nullptr;
            ap1 = (t1 >= 0) ? A + (long)t1 * K : nullptr;
        } else {
            ap0 = A + (long)r0 * K;
            ap1 = A + (long)r1 * K;
        }
    }
    const float* bp = B + (long)bx * 128 + bcol;

    float acc[8][8];
    #pragma unroll
    for (int i = 0; i < 8; i++)
        #pragma unroll
        for (int j = 0; j < 8; j++) acc[i][j] = 0.f;

    const int tr = (tid >> 4) << 3;
    const int tc = (tid & 15) << 3;

    for (int k0 = 0; k0 < K; k0 += 16) {
        float4 a0 = ap0 ? *(const float4*)(ap0 + k0 + acol) : make_float4(0.f,0.f,0.f,0.f);
        float4 a1 = ap1 ? *(const float4*)(ap1 + k0 + acol) : make_float4(0.f,0.f,0.f,0.f);
        As[acol+0][arow]    = a0.x;
        As[acol+1][arow]    = a0.y;
        As[acol+2][arow]    = a0.z;
        As[acol+3][arow]    = a0.w;
        As[acol+0][arow+64] = a1.x;
        As[acol+1][arow+64] = a1.y;
        As[acol+2][arow+64] = a1.z;
        As[acol+3][arow+64] = a1.w;
        float4 b0 = *(const float4*)(bp + (long)(k0 + brow)     * N);
        float4 b1 = *(const float4*)(bp + (long)(k0 + brow + 8) * N);
        *(float4*)&Bs[brow][bcol]     = b0;
        *(float4*)&Bs[brow + 8][bcol] = b1;
        __syncthreads();
        #pragma unroll
        for (int k = 0; k < 16; k++) {
            float4 m0 = *(const float4*)&As[k][tr];
            float4 m1 = *(const float4*)&As[k][tr + 4];
            float4 n0 = *(const float4*)&Bs[k][tc];
            float4 n1 = *(const float4*)&Bs[k][tc + 4];
            float rm[8] = {m0.x, m0.y, m0.z, m0.w, m1.x, m1.y, m1.z, m1.w};
            float rn[8] = {n0.x, n0.y, n0.z, n0.w, n1.x, n1.y, n1.z, n1.w};
            #pragma unroll
            for (int i = 0; i < 8; i++)
                #pragma unroll
                for (int j = 0; j < 8; j++)
                    acc[i][j] += rm[i] * rn[j];
        }
        __syncthreads();
    }

    #pragma unroll
    for (int i = 0; i < 8; i++) {
        int gm = by * 128 + tr + i;
        int gn = bx * 128 + tc;
        if (MODE == 0) {
            float* cp = C + (long)gm * N + gn;
            #pragma unroll
            for (int j = 0; j < 8; j++)
                cp[j] = acc[i][j] + (bias ? bias[gn + j] : 0.f);
        } else if (MODE == 1) {
            float* cp = C + (long)gm * N + gn;
            #pragma unroll
            for (int j = 0; j < 8; j++)
                cp[j] = cp[j] + acc[i][j] + bias[gn + j];
        } else if (MODE == 2) {
            float* cp = C + (long)gm * N + gn;
            #pragma unroll
            for (int j = 0; j < 8; j++)
                cp[j] = gelu_exact(acc[i][j] + bias[gn + j]);
        } else {
            int t = rowmap[gm];
            if (t >= 0) {
                float w = topw[t];
                float* cp = C + (long)t * N + gn;
                #pragma unroll
                for (int j = 0; j < 8; j++)
                    cp[j] += w * (acc[i][j] + bias[gn + j]);
            }
        }
    }
}

// ---------------- fused flash attention ----------------
// One block per (b, h, 64-row query tile). Online softmax, K/V tiles of 64.
// smem: Qt (transposed, swizzled), KPt (K then reused for P), Vs (natural).
// Both GEMMs use the 4-LDS.128 / 64-FMA pattern of sgemm_k.

// scalar swizzled index: element (d, r) of a 64x64 transposed tile
__device__ __forceinline__ int fa_swz(int d, int r) {
    return d * 64 + ((((r >> 2) ^ (d & 15)) << 2) | (r & 3));
}
// float4 read of rows r4*4..r4*4+3 at depth d
__device__ __forceinline__ float4 fa_ld4(const float* buf, int d, int r4) {
    return *(const float4*)(buf + d * 64 + ((r4 ^ (d & 15)) << 2));
}

__global__ void __launch_bounds__(256) flash_attn_kernel()
{
    __shared__ float Qt[64*64];
    __shared__ float KPt[64*64];
    __shared__ float Vs[64*64];
    const int qt = blockIdx.x;     // 0..15
    const int bh = blockIdx.y;     // 0..15
    const int b = bh >> 3, h = bh & 7;
    const int tid = threadIdx.x;
    const int tr = (tid >> 4) << 2;     // row base (0..60)
    const int tc = (tid & 15) << 2;     // col base (0..60)
    const int r4q = tr >> 2;
    const int c4  = tc >> 2;

    // load Q tile (64 x 64) transposed + swizzled
    const float* Qbase = g_qkv + ((size_t)(b * SEQ + qt * 64)) * 1536 + h * DHD;
    #pragma unroll
    for (int rep = 0; rep < 4; rep++) {
        int idx = rep * 256 + tid;
        int row = idx >> 4;
        int d4  = (idx & 15) << 2;
        float4 v = *(const float4*)(Qbase + (size_t)row * 1536 + d4);
        Qt[fa_swz(d4+0, row)] = v.x;
        Qt[fa_swz(d4+1, row)] = v.y;
        Qt[fa_swz(d4+2, row)] = v.z;
        Qt[fa_swz(d4+3, row)] = v.w;
    }

    float m[4], l[4], acc[4][4];
    #pragma unroll
    for (int i = 0; i < 4; i++) {
        m[i] = -1e30f; l[i] = 0.f;
        #pragma unroll
        for (int j = 0; j < 4; j++) acc[i][j] = 0.f;
    }

    for (int kt = 0; kt <= qt; kt++) {
        __syncthreads();   // previous iter done reading KPt/Vs (and Q visible, iter 0)
        const float* Kbase = g_qkv + ((size_t)(b * SEQ + kt * 64)) * 1536 + DIM + h * DHD;
        const float* Vbase = Kbase + DIM;
        #pragma unroll
        for (int rep = 0; rep < 4; rep++) {
            int idx = rep * 256 + tid;
            int row = idx >> 4;
            int d4  = (idx & 15) << 2;
            float4 kv = *(const float4*)(Kbase + (size_t)row * 1536 + d4);
            KPt[fa_swz(d4+0, row)] = kv.x;
            KPt[fa_swz(d4+1, row)] = kv.y;
            KPt[fa_swz(d4+2, row)] = kv.z;
            KPt[fa_swz(d4+3, row)] = kv.w;
            float4 vv = *(const float4*)(Vbase + (size_t)row * 1536 + d4);
            *(float4*)(Vs + row * 64 + d4) = vv;
        }
        __syncthreads();

        // S = Q K^T  (4x4 per thread)
        float s[4][4];
        #pragma unroll
        for (int i = 0; i < 4; i++)
            #pragma unroll
            for (int j = 0; j < 4; j++) s[i][j] = 0.f;
        #pragma unroll 8
        for (int d = 0; d < DHD; d++) {
            float4 qv = fa_ld4(Qt,  d, r4q);
            float4 kv = fa_ld4(KPt, d, c4);
            float rq[4] = {qv.x, qv.y, qv.z, qv.w};
            float rk[4] = {kv.x, kv.y, kv.z, kv.w};
            #pragma unroll
            for (int i = 0; i < 4; i++)
                #pragma unroll
                for (int j = 0; j < 4; j++)
                    s[i][j] += rq[i] * rk[j];
        }

        // scale + causal mask (diagonal tile only)
        #pragma unroll
        for (int i = 0; i < 4; i++)
            #pragma unroll
            for (int j = 0; j < 4; j++) {
                s[i][j] *= 0.125f;
                if (kt == qt && (tc + j) > (tr + i)) s[i][j] = -1e30f;
            }

        // online softmax update
        float tm[4];
        #pragma unroll
        for (int i = 0; i < 4; i++) {
            tm[i] = fmaxf(fmaxf(s[i][0], s[i][1]), fmaxf(s[i][2], s[i][3]));
            #pragma unroll
            for (int o = 8; o > 0; o >>= 1)
                tm[i] = fmaxf(tm[i], __shfl_xor_sync(0xffffffffu, tm[i], o, 16));
        }
        #pragma unroll
        for (int i = 0; i < 4; i++) {
            float mn  = fmaxf(m[i], tm[i]);
            float fac = expf(m[i] - mn);
            m[i] = mn;
            l[i] *= fac;
            #pragma unroll
            for (int j = 0; j < 4; j++) acc[i][j] *= fac;
            float rs = 0.f;
            #pragma unroll
            for (int j = 0; j < 4; j++) {
                float p = expf(s[i][j] - mn);
                s[i][j] = p;
                rs += p;
            }
            #pragma unroll
            for (int o = 8; o > 0; o >>= 1)
                rs += __shfl_xor_sync(0xffffffffu, rs, o, 16);
            l[i] += rs;
        }

        __syncthreads();   // all warps done reading KPt as K
        // store P transposed into KPt: column (tc+j), rows tr..tr+3 as float4
        #pragma unroll
        for (int j = 0; j < 4; j++) {
            int d = tc + j;
            *(float4*)(KPt + d * 64 + ((r4q ^ (d & 15)) << 2)) =
                make_float4(s[0][j], s[1][j], s[2][j], s[3][j]);
        }
        __syncthreads();

        // O += P V
        #pragma unroll 8
        for (int j2 = 0; j2 < 64; j2++) {
            float4 pv = fa_ld4(KPt, j2, r4q);
            float4 vv = *(const float4*)(Vs + j2 * 64 + tc);
            float rp[4] = {pv.x, pv.y, pv.z, pv.w};
            #pragma unroll
            for (int i = 0; i < 4; i++) {
                acc[i][0] += rp[i] * vv.x;
                acc[i][1] += rp[i] * vv.y;
                acc[i][2] += rp[i] * vv.z;
                acc[i][3] += rp[i] * vv.w;
            }
        }
    }

    // epilogue: normalize and write O
    #pragma unroll
    for (int i = 0; i < 4; i++) {
        float inv = 1.0f / l[i];
        int q = qt * 64 + tr + i;
        float4 o = make_float4(acc[i][0]*inv, acc[i][1]*inv, acc[i][2]*inv, acc[i][3]*inv);
        *(float4*)(g_o + ((size_t)(b * SEQ + q)) * DIM + h * DHD + tc) = o;
    }
}

// ---------------- router ----------------
__global__ __launch_bounds__(32) void zero_router_kernel()
{
    if (threadIdx.x < NEXP) g_cnt[threadIdx.x] = 0;
}

__global__ __launch_bounds__(128) void router_kernel(
    const float* __restrict__ rW, const float* __restrict__ rb,
    float* __restrict__ rl_out)
{
    int t = blockIdx.x;
    int tid = threadIdx.x;
    float acc[NEXP];
    #pragma unroll
    for (int e = 0; e < NEXP; e++) acc[e] = 0.f;
    for (int k = tid; k < DIM; k += 128) {
        float hv = g_h[(size_t)t * DIM + k];
        const float* r = rW + (size_t)k * NEXP;
        float4 r0 = *(const float4*)(r);
        float4 r1 = *(const float4*)(r + 4);
        acc[0] += hv * r0.x; acc[1] += hv * r0.y; acc[2] += hv * r0.z; acc[3] += hv * r0.w;
        acc[4] += hv * r1.x; acc[5] += hv * r1.y; acc[6] += hv * r1.z; acc[7] += hv * r1.w;
    }
    __shared__ float red[4][NEXP];
    int lane = tid & 31, w = tid >> 5;
    #pragma unroll
    for (int e = 0; e < NEXP; e++)
        #pragma unroll
        for (int o = 16; o > 0; o >>= 1)
            acc[e] += __shfl_down_sync(0xffffffffu, acc[e], o);
    if (lane == 0)
        #pragma unroll
        for (int e = 0; e < NEXP; e++) red[w][e] = acc[e];
    __syncthreads();
    if (tid == 0) {
        float rl[NEXP], p[NEXP];
        #pragma unroll
        for (int e = 0; e < NEXP; e++)
            rl[e] = red[0][e] + red[1][e] + red[2][e] + red[3][e] + rb[e];
        #pragma unroll
        for (int e = 0; e < NEXP; e++) rl_out[(size_t)t * NEXP + e] = rl[e];
        float m = rl[0];
        #pragma unroll
        for (int e = 1; e < NEXP; e++) m = fmaxf(m, rl[e]);
        float s = 0.f;
        #pragma unroll
        for (int e = 0; e < NEXP; e++) { p[e] = expf(rl[e] - m); s += p[e]; }
        float inv = 1.0f / s;
        float best = -1.f; int bi = 0;
        #pragma unroll
        for (int e = 0; e < NEXP; e++) {
            p[e] *= inv;
            g_pe[(size_t)t * NEXP + e] = p[e];
            if (p[e] > best) { best = p[e]; bi = e; }
        }
        g_topi[t] = bi;
        g_topw[t] = best;
        atomicAdd(&g_cnt[bi], 1);
    }
}

// deterministic per-expert prob sums (fixed reduction tree, no float atomics)
__global__ __launch_bounds__(256) void expert_sum_kernel()
{
    int e = blockIdx.x;
    float s = 0.f;
    for (int t = threadIdx.x; t < TKN; t += blockDim.x)
        s += g_pe[(size_t)t * NEXP + e];
    s = block_reduce_sum(s);
    if (threadIdx.x == 0) g_sp[e] = s;
}

__global__ __launch_bounds__(128) void moe_setup_kernel()
{
    int tid = threadIdx.x;
    for (int i = tid; i < MAXROWS; i += blockDim.x) g_perm[i] = -1;
    if (tid < NEXP) g_cursor[tid] = 0;
    __syncthreads();
    if (tid == 0) {
        int off = 0, tile = 0;
        float aux = 0.f;
        for (int e = 0; e < NEXP; e++) {
            g_padoff[e] = off;
            int c = g_cnt[e];
            aux += (float)c * g_sp[e];
            int nt = (c + 127) >> 7;
            for (int k = 0; k < nt; k++) g_tileexp[tile++] = e;
            off += nt << 7;
        }
        for (; tile < MAXTILES; tile++) g_tileexp[tile] = -1;
        g_aux[0] += (float)NEXP * aux / ((float)TKN * (float)TKN);
    }
}

__global__ __launch_bounds__(128) void scatter_kernel()
{
    int t = blockIdx.x * blockDim.x + threadIdx.x;
    if (t >= TKN) return;
    int e = g_topi[t];
    int pos = atomicAdd(&g_cursor[e], 1);
    g_perm[g_padoff[e] + pos] = t;
}

__global__ void write_aux_kernel(float* __restrict__ out)
{
    out[0] = g_aux[0];
}

// ---------------- launch ----------------
extern "C" void kernel_launch(void* const* d_in, const int* in_sizes, int n_in,
                              void* d_out, int out_size)
{
    const int*   ids  = (const int*)  d_in[0];
    const float* tok  = (const float*)d_in[1];
    const float* pos  = (const float*)d_in[2];
    const float* Wqkv = (const float*)d_in[3];
    const float* bqkv = (const float*)d_in[4];
    const float* Wo   = (const float*)d_in[5];
    const float* bo   = (const float*)d_in[6];
    const float* rW   = (const float*)d_in[7];
    const float* rb   = (const float*)d_in[8];
    const float* eW1  = (const float*)d_in[9];
    const float* eb1  = (const float*)d_in[10];
    const float* eW2  = (const float*)d_in[11];
    const float* eb2  = (const float*)d_in[12];
    const float* n1w  = (const float*)d_in[13];
    const float* n2w  = (const float*)d_in[14];
    const float* noww = (const float*)d_in[15];
    const float* lmW  = (const float*)d_in[16];
    float* out = (float*)d_out;

    void *px, *ph, *pqkv, *po, *phid, *pperm, *ptile, *ptopw;
    cudaGetSymbolAddress(&px,   g_x);
    cudaGetSymbolAddress(&ph,   g_h);
    cudaGetSymbolAddress(&pqkv, g_qkv);
    cudaGetSymbolAddress(&po,   g_o);
    cudaGetSymbolAddress(&phid, g_hid);
    cudaGetSymbolAddress(&pperm, g_perm);
    cudaGetSymbolAddress(&ptile, g_tileexp);
    cudaGetSymbolAddress(&ptopw, g_topw);
    float* x   = (float*)px;
    float* h   = (float*)ph;
    float* qkv = (float*)pqkv;
    float* o   = (float*)po;
    float* hid = (float*)phid;

    embed_kernel<<<TKN, 128>>>(ids, tok, pos);

    for (int l = 0; l < NLAYER; l++) {
        // attention block
        rmsnorm_kernel<<<TKN, 128>>>(x, n1w + (size_t)l * DIM, h);
        sgemm_k<0><<<dim3(12, 16), 256>>>(3 * DIM, DIM,
            h, Wqkv + (size_t)l * DIM * 3 * DIM, bqkv + (size_t)l * 3 * DIM,
            qkv, nullptr, nullptr, 0, 0, nullptr);
        flash_attn_kernel<<<dim3(16, BATCH * NH), 256>>>();
        sgemm_k<1><<<dim3(4, 16), 256>>>(DIM, DIM,
            o, Wo + (size_t)l * DIM * DIM, bo + (size_t)l * DIM,
            x, nullptr, nullptr, 0, 0, nullptr);

        // MoE block
        rmsnorm_kernel<<<TKN, 128>>>(x, n2w + (size_t)l * DIM, h);
        zero_router_kernel<<<1, 32>>>();
        router_kernel<<<TKN, 128>>>(rW + (size_t)l * DIM * NEXP,
                                    rb + (size_t)l * NEXP,
                                    out + RL_OFF + (size_t)l * TKN * NEXP);
        expert_sum_kernel<<<NEXP, 256>>>();
        moe_setup_kernel<<<1, 128>>>();
        scatter_kernel<<<16, 128>>>();

        sgemm_k<2><<<dim3(16, MAXTILES), 256>>>(FFD, DIM,
            h, eW1 + (size_t)l * NEXP * DIM * FFD, eb1 + (size_t)l * NEXP * FFD,
            hid, (const int*)pperm, (const int*)ptile,
            (long)DIM * FFD, (long)FFD, nullptr);
        sgemm_k<3><<<dim3(4, MAXTILES), 256>>>(DIM, FFD,
            hid, eW2 + (size_t)l * NEXP * FFD * DIM, eb2 + (size_t)l * NEXP * DIM,
            x, (const int*)pperm, (const int*)ptile,
            (long)FFD * DIM, (long)DIM, (const float*)ptopw);
    }

    // final norm + LM head
    rmsnorm_kernel<<<TKN, 128>>>(x, noww, h);
    sgemm_k<0><<<dim3(VOC / 128, 16), 256>>>(VOC, DIM,
        h, lmW, nullptr, out, nullptr, nullptr, 0, 0, nullptr);
    write_aux_kernel<<<1, 1>>>(out + AUX_OFF);
}

// round 4
// speedup vs baseline: 1.7014x; 1.1752x over previous
#include <cuda_runtime.h>
#include <cstddef>
#include <math.h>

// ---------------- problem constants ----------------
#define TKN     2048            // B*S
#define BATCH   2
#define SEQ     1024
#define DIM     512
#define NH      8
#define DHD     64
#define NLAYER  12
#define NEXP    8
#define FFD     2048
#define VOC     32000
#define MAXTILES 24
#define MAXROWS  (MAXTILES*128)

// output layout: [logits (B*S*V)] [aux (1)] [rlogits (L*B*S*E)]
#define LOGITS_N ((size_t)BATCH*SEQ*VOC)
#define AUX_OFF  LOGITS_N
#define RL_OFF   (LOGITS_N + 1)

// ---------------- scratch ----------------
__device__ float g_x[TKN*DIM];
__device__ float g_h[TKN*DIM];
__device__ float g_qkv[TKN*3*DIM];
__device__ float g_o[TKN*DIM];
__device__ float g_hid[(size_t)MAXROWS*FFD];
__device__ float g_pe[TKN*NEXP];
__device__ int   g_topi[TKN];
__device__ float g_topw[TKN];
__device__ int   g_cnt[NEXP];
__device__ float g_sp[NEXP];
__device__ int   g_padoff[NEXP];
__device__ int   g_cursor[NEXP];
__device__ int   g_tileexp[MAXTILES];
__device__ int   g_perm[MAXROWS];
__device__ float g_aux[1];

// ---------------- helpers ----------------
__device__ __forceinline__ float gelu_exact(float x) {
    return 0.5f * x * (1.0f + erff(x * 0.70710678118654752f));
}

__device__ __forceinline__ unsigned f2tf(float x) {
    unsigned r;
    asm("cvt.rna.tf32.f32 %0, %1;" : "=r"(r) : "f"(x));
    return r;
}

__device__ __forceinline__ void mma_tf32(float* c, const unsigned* a, const unsigned* b) {
    asm volatile(
        "mma.sync.aligned.m16n8k8.row.col.f32.tf32.tf32.f32 "
        "{%0,%1,%2,%3}, {%4,%5,%6,%7}, {%8,%9}, {%0,%1,%2,%3};"
        : "+f"(c[0]), "+f"(c[1]), "+f"(c[2]), "+f"(c[3])
        : "r"(a[0]), "r"(a[1]), "r"(a[2]), "r"(a[3]),
          "r"(b[0]), "r"(b[1]));
}

__device__ __forceinline__ float block_reduce_sum(float v) {
    __shared__ float sb[33];
    __syncthreads();
    int lane = threadIdx.x & 31, wid = threadIdx.x >> 5;
    #pragma unroll
    for (int o = 16; o > 0; o >>= 1) v += __shfl_down_sync(0xffffffffu, v, o);
    if (lane == 0) sb[wid] = v;
    __syncthreads();
    if (threadIdx.x == 0) {
        float s = 0.f;
        int nw = blockDim.x >> 5;
        for (int i = 0; i < nw; i++) s += sb[i];
        sb[32] = s;
    }
    __syncthreads();
    return sb[32];
}

// ---------------- embedding ----------------
__global__ __launch_bounds__(128) void embed_kernel(
    const int* __restrict__ ids, const float* __restrict__ tok,
    const float* __restrict__ pos)
{
    int t = blockIdx.x;
    int tid = threadIdx.x;
    if (t == 0 && tid == 0) g_aux[0] = 0.f;
    int id = ids[t];
    int s  = t & (SEQ - 1);
    float4 a = ((const float4*)(tok + (size_t)id * DIM))[tid];
    float4 b = ((const float4*)(pos + (size_t)s  * DIM))[tid];
    float4 o; o.x = a.x + b.x; o.y = a.y + b.y; o.z = a.z + b.z; o.w = a.w + b.w;
    ((float4*)(g_x + (size_t)t * DIM))[tid] = o;
}

// ---------------- rmsnorm ----------------
__global__ __launch_bounds__(128) void rmsnorm_kernel(
    const float* __restrict__ X, const float* __restrict__ w, float* __restrict__ Y)
{
    int t = blockIdx.x;
    int tid = threadIdx.x;
    float4 v = ((const float4*)(X + (size_t)t * DIM))[tid];
    float ss = v.x*v.x + v.y*v.y + v.z*v.z + v.w*v.w;
    ss = block_reduce_sum(ss);
    float scale = rsqrtf(ss * (1.0f / DIM) + 1e-6f);
    float4 wv = ((const float4*)w)[tid];
    float4 o;
    o.x = v.x * scale * wv.x;
    o.y = v.y * scale * wv.y;
    o.z = v.z * scale * wv.z;
    o.w = v.w * scale * wv.w;
    ((float4*)(Y + (size_t)t * DIM))[tid] = o;
}

// ---------------- generic SGEMM 128x128x16 (FFMA, fp32-exact) ------------
template <int MODE>
__global__ void __launch_bounds__(256) sgemm_k(
    int N, int K,
    const float* __restrict__ A,
    const float* __restrict__ B,
    const float* __restrict__ bias,
    float* __restrict__ C,
    const int* __restrict__ rowmap,
    const int* __restrict__ tileexp,
    long bStride, long biasStride,
    const float* __restrict__ topw)
{
    const int bx = blockIdx.x;
    const int by = blockIdx.y;
    if (MODE == 2 || MODE == 3) {
        int e = tileexp[by];
        if (e < 0) return;
        B    += (long)e * bStride;
        bias += (long)e * biasStride;
    }
    __shared__ float As[16][128];
    __shared__ float Bs[16][128];
    const int tid  = threadIdx.x;
    const int arow = tid >> 2;
    const int acol = (tid & 3) << 2;
    const int brow = tid >> 5;
    const int bcol = (tid & 31) << 2;

    const float* ap0; const float* ap1;
    {
        int r0 = by * 128 + arow;
        int r1 = r0 + 64;
        if (MODE == 2) {
            int t0 = rowmap[r0];
            int t1 = rowmap[r1];
            ap0 = (t0 >= 0) ? A + (long)t0 * K : nullptr;
            ap1 = (t1 >= 0) ? A + (long)t1 * K : nullptr;
        } else {
            ap0 = A + (long)r0 * K;
            ap1 = A + (long)r1 * K;
        }
    }
    const float* bp = B + (long)bx * 128 + bcol;

    float acc[8][8];
    #pragma unroll
    for (int i = 0; i < 8; i++)
        #pragma unroll
        for (int j = 0; j < 8; j++) acc[i][j] = 0.f;

    const int tr = (tid >> 4) << 3;
    const int tc = (tid & 15) << 3;

    for (int k0 = 0; k0 < K; k0 += 16) {
        float4 a0 = ap0 ? *(const float4*)(ap0 + k0 + acol) : make_float4(0.f,0.f,0.f,0.f);
        float4 a1 = ap1 ? *(const float4*)(ap1 + k0 + acol) : make_float4(0.f,0.f,0.f,0.f);
        As[acol+0][arow]    = a0.x;
        As[acol+1][arow]    = a0.y;
        As[acol+2][arow]    = a0.z;
        As[acol+3][arow]    = a0.w;
        As[acol+0][arow+64] = a1.x;
        As[acol+1][arow+64] = a1.y;
        As[acol+2][arow+64] = a1.z;
        As[acol+3][arow+64] = a1.w;
        float4 b0 = *(const float4*)(bp + (long)(k0 + brow)     * N);
        float4 b1 = *(const float4*)(bp + (long)(k0 + brow + 8) * N);
        *(float4*)&Bs[brow][bcol]     = b0;
        *(float4*)&Bs[brow + 8][bcol] = b1;
        __syncthreads();
        #pragma unroll
        for (int k = 0; k < 16; k++) {
            float4 m0 = *(const float4*)&As[k][tr];
            float4 m1 = *(const float4*)&As[k][tr + 4];
            float4 n0 = *(const float4*)&Bs[k][tc];
            float4 n1 = *(const float4*)&Bs[k][tc + 4];
            float rm[8] = {m0.x, m0.y, m0.z, m0.w, m1.x, m1.y, m1.z, m1.w};
            float rn[8] = {n0.x, n0.y, n0.z, n0.w, n1.x, n1.y, n1.z, n1.w};
            #pragma unroll
            for (int i = 0; i < 8; i++)
                #pragma unroll
                for (int j = 0; j < 8; j++)
                    acc[i][j] += rm[i] * rn[j];
        }
        __syncthreads();
    }

    #pragma unroll
    for (int i = 0; i < 8; i++) {
        int gm = by * 128 + tr + i;
        int gn = bx * 128 + tc;
        if (MODE == 0) {
            float* cp = C + (long)gm * N + gn;
            #pragma unroll
            for (int j = 0; j < 8; j++)
                cp[j] = acc[i][j] + (bias ? bias[gn + j] : 0.f);
        } else if (MODE == 1) {
            float* cp = C + (long)gm * N + gn;
            #pragma unroll
            for (int j = 0; j < 8; j++)
                cp[j] = cp[j] + acc[i][j] + bias[gn + j];
        } else if (MODE == 2) {
            float* cp = C + (long)gm * N + gn;
            #pragma unroll
            for (int j = 0; j < 8; j++)
                cp[j] = gelu_exact(acc[i][j] + bias[gn + j]);
        } else {
            int t = rowmap[gm];
            if (t >= 0) {
                float w = topw[t];
                float* cp = C + (long)t * N + gn;
                #pragma unroll
                for (int j = 0; j < 8; j++)
                    cp[j] += w * (acc[i][j] + bias[gn + j]);
            }
        }
    }
}

// ---------------- LM head: tf32 tensor-core GEMM (no bias) ----------------
// C[M=2048, N=32000] = A[2048,512] @ B[512,32000]
// block 128x128, 8 warps of 64x32, m16n8k8 tf32 mma, smem pad 136 (conflict-free frags)
__global__ void __launch_bounds__(256) lm_head_tf32_kernel(
    const float* __restrict__ A, const float* __restrict__ B, float* __restrict__ C)
{
    const int N = VOC, K = DIM;
    const int bx = blockIdx.x;   // 0..249
    const int by = blockIdx.y;   // 0..15
    __shared__ unsigned As[16][136];
    __shared__ unsigned Bs[16][136];
    const int tid  = threadIdx.x;
    const int wid  = tid >> 5;
    const int lane = tid & 31;
    const int WM = (wid >> 2) * 64;     // 0 / 64
    const int WN = (wid & 3) * 32;      // 0 / 32 / 64 / 96
    const int g  = lane >> 2;           // 0..7
    const int tg = lane & 3;            // 0..3

    const int arow = tid >> 2;          // 0..63
    const int acol = (tid & 3) << 2;
    const int brow = tid >> 5;          // 0..7
    const int bcol = (tid & 31) << 2;

    const float* ap0 = A + (long)(by * 128 + arow) * K;
    const float* ap1 = ap0 + (long)64 * K;
    const float* bp  = B + (long)bx * 128 + bcol;

    float acc[4][4][4];
    #pragma unroll
    for (int mt = 0; mt < 4; mt++)
        #pragma unroll
        for (int nt = 0; nt < 4; nt++)
            #pragma unroll
            for (int r = 0; r < 4; r++) acc[mt][nt][r] = 0.f;

    for (int k0 = 0; k0 < K; k0 += 16) {
        float4 a0 = *(const float4*)(ap0 + k0 + acol);
        float4 a1 = *(const float4*)(ap1 + k0 + acol);
        As[acol+0][arow]    = f2tf(a0.x);
        As[acol+1][arow]    = f2tf(a0.y);
        As[acol+2][arow]    = f2tf(a0.z);
        As[acol+3][arow]    = f2tf(a0.w);
        As[acol+0][arow+64] = f2tf(a1.x);
        As[acol+1][arow+64] = f2tf(a1.y);
        As[acol+2][arow+64] = f2tf(a1.z);
        As[acol+3][arow+64] = f2tf(a1.w);
        float4 b0 = *(const float4*)(bp + (long)(k0 + brow)     * N);
        float4 b1 = *(const float4*)(bp + (long)(k0 + brow + 8) * N);
        {
            uint4 v0 = make_uint4(f2tf(b0.x), f2tf(b0.y), f2tf(b0.z), f2tf(b0.w));
            uint4 v1 = make_uint4(f2tf(b1.x), f2tf(b1.y), f2tf(b1.z), f2tf(b1.w));
            *(uint4*)&Bs[brow][bcol]     = v0;
            *(uint4*)&Bs[brow + 8][bcol] = v1;
        }
        __syncthreads();

        #pragma unroll
        for (int kk = 0; kk < 16; kk += 8) {
            unsigned afr[4][4];
            #pragma unroll
            for (int mt = 0; mt < 4; mt++) {
                int m0 = WM + mt * 16;
                afr[mt][0] = As[kk + tg]    [m0 + g];
                afr[mt][1] = As[kk + tg]    [m0 + 8 + g];
                afr[mt][2] = As[kk + 4 + tg][m0 + g];
                afr[mt][3] = As[kk + 4 + tg][m0 + 8 + g];
            }
            unsigned bfr[4][2];
            #pragma unroll
            for (int nt = 0; nt < 4; nt++) {
                int n0 = WN + nt * 8;
                bfr[nt][0] = Bs[kk + tg]    [n0 + g];
                bfr[nt][1] = Bs[kk + 4 + tg][n0 + g];
            }
            #pragma unroll
            for (int mt = 0; mt < 4; mt++)
                #pragma unroll
                for (int nt = 0; nt < 4; nt++)
                    mma_tf32(acc[mt][nt], afr[mt], bfr[nt]);
        }
        __syncthreads();
    }

    #pragma unroll
    for (int mt = 0; mt < 4; mt++) {
        int r0 = by * 128 + WM + mt * 16 + g;
        #pragma unroll
        for (int nt = 0; nt < 4; nt++) {
            int c0 = bx * 128 + WN + nt * 8 + tg * 2;
            *(float2*)(C + (long)r0 * N + c0)       = make_float2(acc[mt][nt][0], acc[mt][nt][1]);
            *(float2*)(C + (long)(r0 + 8) * N + c0) = make_float2(acc[mt][nt][2], acc[mt][nt][3]);
        }
    }
}

// ---------------- fused flash attention (work-paired: qt=bx and 15-bx) -------
__device__ __forceinline__ int fa_swz(int d, int r) {
    return d * 64 + ((((r >> 2) ^ (d & 15)) << 2) | (r & 3));
}
__device__ __forceinline__ float4 fa_ld4(const float* buf, int d, int r4) {
    return *(const float4*)(buf + d * 64 + ((r4 ^ (d & 15)) << 2));
}

__global__ void __launch_bounds__(256) flash_attn_kernel()
{
    __shared__ float Qt[64*64];
    __shared__ float KPt[64*64];
    __shared__ float Vs[64*64];
    const int bh = blockIdx.y;     // 0..15
    const int b = bh >> 3, h = bh & 7;
    const int tid = threadIdx.x;
    const int tr = (tid >> 4) << 2;
    const int tc = (tid & 15) << 2;
    const int r4q = tr >> 2;
    const int c4  = tc >> 2;

    for (int pass = 0; pass < 2; pass++) {
        const int qt = pass ? (15 - (int)blockIdx.x) : (int)blockIdx.x;  // balanced pair
        // load Q tile (64 x 64) transposed + swizzled
        const float* Qbase = g_qkv + ((size_t)(b * SEQ + qt * 64)) * 1536 + h * DHD;
        #pragma unroll
        for (int rep = 0; rep < 4; rep++) {
            int idx = rep * 256 + tid;
            int row = idx >> 4;
            int d4  = (idx & 15) << 2;
            float4 v = *(const float4*)(Qbase + (size_t)row * 1536 + d4);
            Qt[fa_swz(d4+0, row)] = v.x;
            Qt[fa_swz(d4+1, row)] = v.y;
            Qt[fa_swz(d4+2, row)] = v.z;
            Qt[fa_swz(d4+3, row)] = v.w;
        }

        float m[4], l[4], acc[4][4];
        #pragma unroll
        for (int i = 0; i < 4; i++) {
            m[i] = -1e30f; l[i] = 0.f;
            #pragma unroll
            for (int j = 0; j < 4; j++) acc[i][j] = 0.f;
        }

        for (int kt = 0; kt <= qt; kt++) {
            __syncthreads();   // prev iter / prev pass done with smem
            const float* Kbase = g_qkv + ((size_t)(b * SEQ + kt * 64)) * 1536 + DIM + h * DHD;
            const float* Vbase = Kbase + DIM;
            #pragma unroll
            for (int rep = 0; rep < 4; rep++) {
                int idx = rep * 256 + tid;
                int row = idx >> 4;
                int d4  = (idx & 15) << 2;
                float4 kv = *(const float4*)(Kbase + (size_t)row * 1536 + d4);
                KPt[fa_swz(d4+0, row)] = kv.x;
                KPt[fa_swz(d4+1, row)] = kv.y;
                KPt[fa_swz(d4+2, row)] = kv.z;
                KPt[fa_swz(d4+3, row)] = kv.w;
                float4 vv = *(const float4*)(Vbase + (size_t)row * 1536 + d4);
                *(float4*)(Vs + row * 64 + d4) = vv;
            }
            __syncthreads();

            float s[4][4];
            #pragma unroll
            for (int i = 0; i < 4; i++)
                #pragma unroll
                for (int j = 0; j < 4; j++) s[i][j] = 0.f;
            #pragma unroll 8
            for (int d = 0; d < DHD; d++) {
                float4 qv = fa_ld4(Qt,  d, r4q);
                float4 kv = fa_ld4(KPt, d, c4);
                float rq[4] = {qv.x, qv.y, qv.z, qv.w};
                float rk[4] = {kv.x, kv.y, kv.z, kv.w};
                #pragma unroll
                for (int i = 0; i < 4; i++)
                    #pragma unroll
                    for (int j = 0; j < 4; j++)
                        s[i][j] += rq[i] * rk[j];
            }

            #pragma unroll
            for (int i = 0; i < 4; i++)
                #pragma unroll
                for (int j = 0; j < 4; j++) {
                    s[i][j] *= 0.125f;
                    if (kt == qt && (tc + j) > (tr + i)) s[i][j] = -1e30f;
                }

            float tm[4];
            #pragma unroll
            for (int i = 0; i < 4; i++) {
                tm[i] = fmaxf(fmaxf(s[i][0], s[i][1]), fmaxf(s[i][2], s[i][3]));
                #pragma unroll
                for (int o = 8; o > 0; o >>= 1)
                    tm[i] = fmaxf(tm[i], __shfl_xor_sync(0xffffffffu, tm[i], o, 16));
            }
            #pragma unroll
            for (int i = 0; i < 4; i++) {
                float mn  = fmaxf(m[i], tm[i]);
                float fac = expf(m[i] - mn);
                m[i] = mn;
                l[i] *= fac;
                #pragma unroll
                for (int j = 0; j < 4; j++) acc[i][j] *= fac;
                float rs = 0.f;
                #pragma unroll
                for (int j = 0; j < 4; j++) {
                    float p = expf(s[i][j] - mn);
                    s[i][j] = p;
                    rs += p;
                }
                #pragma unroll
                for (int o = 8; o > 0; o >>= 1)
                    rs += __shfl_xor_sync(0xffffffffu, rs, o, 16);
                l[i] += rs;
            }

            __syncthreads();
            #pragma unroll
            for (int j = 0; j < 4; j++) {
                int d = tc + j;
                *(float4*)(KPt + d * 64 + ((r4q ^ (d & 15)) << 2)) =
                    make_float4(s[0][j], s[1][j], s[2][j], s[3][j]);
            }
            __syncthreads();

            #pragma unroll 8
            for (int j2 = 0; j2 < 64; j2++) {
                float4 pv = fa_ld4(KPt, j2, r4q);
                float4 vv = *(const float4*)(Vs + j2 * 64 + tc);
                float rp[4] = {pv.x, pv.y, pv.z, pv.w};
                #pragma unroll
                for (int i = 0; i < 4; i++) {
                    acc[i][0] += rp[i] * vv.x;
                    acc[i][1] += rp[i] * vv.y;
                    acc[i][2] += rp[i] * vv.z;
                    acc[i][3] += rp[i] * vv.w;
                }
            }
        }

        #pragma unroll
        for (int i = 0; i < 4; i++) {
            float inv = 1.0f / l[i];
            int q = qt * 64 + tr + i;
            float4 o = make_float4(acc[i][0]*inv, acc[i][1]*inv, acc[i][2]*inv, acc[i][3]*inv);
            *(float4*)(g_o + ((size_t)(b * SEQ + q)) * DIM + h * DHD + tc) = o;
        }
        __syncthreads();   // all smem reads done before next pass overwrites Qt
    }
}

// ---------------- router ----------------
__global__ __launch_bounds__(32) void zero_router_kernel()
{
    if (threadIdx.x < NEXP) g_cnt[threadIdx.x] = 0;
}

__global__ __launch_bounds__(128) void router_kernel(
    const float* __restrict__ rW, const float* __restrict__ rb,
    float* __restrict__ rl_out)
{
    int t = blockIdx.x;
    int tid = threadIdx.x;
    float acc[NEXP];
    #pragma unroll
    for (int e = 0; e < NEXP; e++) acc[e] = 0.f;
    for (int k = tid; k < DIM; k += 128) {
        float hv = g_h[(size_t)t * DIM + k];
        const float* r = rW + (size_t)k * NEXP;
        float4 r0 = *(const float4*)(r);
        float4 r1 = *(const float4*)(r + 4);
        acc[0] += hv * r0.x; acc[1] += hv * r0.y; acc[2] += hv * r0.z; acc[3] += hv * r0.w;
        acc[4] += hv * r1.x; acc[5] += hv * r1.y; acc[6] += hv * r1.z; acc[7] += hv * r1.w;
    }
    __shared__ float red[4][NEXP];
    int lane = tid & 31, w = tid >> 5;
    #pragma unroll
    for (int e = 0; e < NEXP; e++)
        #pragma unroll
        for (int o = 16; o > 0; o >>= 1)
            acc[e] += __shfl_down_sync(0xffffffffu, acc[e], o);
    if (lane == 0)
        #pragma unroll
        for (int e = 0; e < NEXP; e++) red[w][e] = acc[e];
    __syncthreads();
    if (tid == 0) {
        float rl[NEXP], p[NEXP];
        #pragma unroll
        for (int e = 0; e < NEXP; e++)
            rl[e] = red[0][e] + red[1][e] + red[2][e] + red[3][e] + rb[e];
        #pragma unroll
        for (int e = 0; e < NEXP; e++) rl_out[(size_t)t * NEXP + e] = rl[e];
        float m = rl[0];
        #pragma unroll
        for (int e = 1; e < NEXP; e++) m = fmaxf(m, rl[e]);
        float s = 0.f;
        #pragma unroll
        for (int e = 0; e < NEXP; e++) { p[e] = expf(rl[e] - m); s += p[e]; }
        float inv = 1.0f / s;
        float best = -1.f; int bi = 0;
        #pragma unroll
        for (int e = 0; e < NEXP; e++) {
            p[e] *= inv;
            g_pe[(size_t)t * NEXP + e] = p[e];
            if (p[e] > best) { best = p[e]; bi = e; }
        }
        g_topi[t] = bi;
        g_topw[t] = best;
        atomicAdd(&g_cnt[bi], 1);
    }
}

__global__ __launch_bounds__(256) void expert_sum_kernel()
{
    int e = blockIdx.x;
    float s = 0.f;
    for (int t = threadIdx.x; t < TKN; t += blockDim.x)
        s += g_pe[(size_t)t * NEXP + e];
    s = block_reduce_sum(s);
    if (threadIdx.x == 0) g_sp[e] = s;
}

__global__ __launch_bounds__(128) void moe_setup_kernel()
{
    int tid = threadIdx.x;
    for (int i = tid; i < MAXROWS; i += blockDim.x) g_perm[i] = -1;
    if (tid < NEXP) g_cursor[tid] = 0;
    __syncthreads();
    if (tid == 0) {
        int off = 0, tile = 0;
        float aux = 0.f;
        for (int e = 0; e < NEXP; e++) {
            g_padoff[e] = off;
            int c = g_cnt[e];
            aux += (float)c * g_sp[e];
            int nt = (c + 127) >> 7;
            for (int k = 0; k < nt; k++) g_tileexp[tile++] = e;
            off += nt << 7;
        }
        for (; tile < MAXTILES; tile++) g_tileexp[tile] = -1;
        g_aux[0] += (float)NEXP * aux / ((float)TKN * (float)TKN);
    }
}

__global__ __launch_bounds__(128) void scatter_kernel()
{
    int t = blockIdx.x * blockDim.x + threadIdx.x;
    if (t >= TKN) return;
    int e = g_topi[t];
    int pos = atomicAdd(&g_cursor[e], 1);
    g_perm[g_padoff[e] + pos] = t;
}

__global__ void write_aux_kernel(float* __restrict__ out)
{
    out[0] = g_aux[0];
}

// ---------------- launch ----------------
extern "C" void kernel_launch(void* const* d_in, const int* in_sizes, int n_in,
                              void* d_out, int out_size)
{
    const int*   ids  = (const int*)  d_in[0];
    const float* tok  = (const float*)d_in[1];
    const float* pos  = (const float*)d_in[2];
    const float* Wqkv = (const float*)d_in[3];
    const float* bqkv = (const float*)d_in[4];
    const float* Wo   = (const float*)d_in[5];
    const float* bo   = (const float*)d_in[6];
    const float* rW   = (const float*)d_in[7];
    const float* rb   = (const float*)d_in[8];
    const float* eW1  = (const float*)d_in[9];
    const float* eb1  = (const float*)d_in[10];
    const float* eW2  = (const float*)d_in[11];
    const float* eb2  = (const float*)d_in[12];
    const float* n1w  = (const float*)d_in[13];
    const float* n2w  = (const float*)d_in[14];
    const float* noww = (const float*)d_in[15];
    const float* lmW  = (const float*)d_in[16];
    float* out = (float*)d_out;

    void *px, *ph, *pqkv, *po, *phid, *pperm, *ptile, *ptopw;
    cudaGetSymbolAddress(&px,   g_x);
    cudaGetSymbolAddress(&ph,   g_h);
    cudaGetSymbolAddress(&pqkv, g_qkv);
    cudaGetSymbolAddress(&po,   g_o);
    cudaGetSymbolAddress(&phid, g_hid);
    cudaGetSymbolAddress(&pperm, g_perm);
    cudaGetSymbolAddress(&ptile, g_tileexp);
    cudaGetSymbolAddress(&ptopw, g_topw);
    float* x   = (float*)px;
    float* h   = (float*)ph;
    float* qkv = (float*)pqkv;
    float* o   = (float*)po;
    float* hid = (float*)phid;

    embed_kernel<<<TKN, 128>>>(ids, tok, pos);

    for (int l = 0; l < NLAYER; l++) {
        // attention block
        rmsnorm_kernel<<<TKN, 128>>>(x, n1w + (size_t)l * DIM, h);
        sgemm_k<0><<<dim3(12, 16), 256>>>(3 * DIM, DIM,
            h, Wqkv + (size_t)l * DIM * 3 * DIM, bqkv + (size_t)l * 3 * DIM,
            qkv, nullptr, nullptr, 0, 0, nullptr);
        flash_attn_kernel<<<dim3(8, BATCH * NH), 256>>>();
        sgemm_k<1><<<dim3(4, 16), 256>>>(DIM, DIM,
            o, Wo + (size_t)l * DIM * DIM, bo + (size_t)l * DIM,
            x, nullptr, nullptr, 0, 0, nullptr);

        // MoE block
        rmsnorm_kernel<<<TKN, 128>>>(x, n2w + (size_t)l * DIM, h);
        zero_router_kernel<<<1, 32>>>();
        router_kernel<<<TKN, 128>>>(rW + (size_t)l * DIM * NEXP,
                                    rb + (size_t)l * NEXP,
                                    out + RL_OFF + (size_t)l * TKN * NEXP);
        expert_sum_kernel<<<NEXP, 256>>>();
        moe_setup_kernel<<<1, 128>>>();
        scatter_kernel<<<16, 128>>>();

        sgemm_k<2><<<dim3(16, MAXTILES), 256>>>(FFD, DIM,
            h, eW1 + (size_t)l * NEXP * DIM * FFD, eb1 + (size_t)l * NEXP * FFD,
            hid, (const int*)pperm, (const int*)ptile,
            (long)DIM * FFD, (long)FFD, nullptr);
        sgemm_k<3><<<dim3(4, MAXTILES), 256>>>(DIM, FFD,
            hid, eW2 + (size_t)l * NEXP * FFD * DIM, eb2 + (size_t)l * NEXP * DIM,
            x, (const int*)pperm, (const int*)ptile,
            (long)FFD * DIM, (long)DIM, (const float*)ptopw);
    }

    // final norm + LM head (tf32 tensor cores; logits are terminal => tf32-safe)
    rmsnorm_kernel<<<TKN, 128>>>(x, noww, h);
    lm_head_tf32_kernel<<<dim3(VOC / 128, 16), 256>>>(h, lmW, out);
    write_aux_kernel<<<1, 1>>>(out + AUX_OFF);
}

// round 8
// speedup vs baseline: 1.7994x; 1.0576x over previous
#include <cuda_runtime.h>
#include <cstddef>
#include <cstdint>
#include <math.h>

// ---------------- problem constants ----------------
#define TKN     2048            // B*S
#define BATCH   2
#define SEQ     1024
#define DIM     512
#define NH      8
#define DHD     64
#define NLAYER  12
#define NEXP    8
#define FFD     2048
#define VOC     32000
#define MAXTILES 24
#define MAXROWS  (MAXTILES*128)

// output layout: [logits (B*S*V)] [aux (1)] [rlogits (L*B*S*E)]
#define LOGITS_N ((size_t)BATCH*SEQ*VOC)
#define AUX_OFF  LOGITS_N
#define RL_OFF   (LOGITS_N + 1)

// ---------------- scratch ----------------
__device__ float g_x[TKN*DIM];
__device__ float g_h[TKN*DIM];
__device__ float g_qkv[TKN*3*DIM];
__device__ float g_o[TKN*DIM];
__device__ float g_hid[(size_t)MAXROWS*FFD];
__device__ float g_pe[TKN*NEXP];
__device__ int   g_topi[TKN];
__device__ float g_topw[TKN];
__device__ int   g_cnt[NEXP];
__device__ float g_sp[NEXP];
__device__ int   g_padoff[NEXP];
__device__ int   g_cursor[NEXP];
__device__ int   g_tileexp[MAXTILES];
__device__ int   g_perm[MAXROWS];
__device__ float g_aux[1];

// ---------------- helpers ----------------
__device__ __forceinline__ float gelu_exact(float x) {
    return 0.5f * x * (1.0f + erff(x * 0.70710678118654752f));
}

__device__ __forceinline__ unsigned f2tf(float x) {
    unsigned r;
    asm("cvt.rna.tf32.f32 %0, %1;" : "=r"(r) : "f"(x));
    return r;
}

__device__ __forceinline__ void mma_tf32(float* c, const unsigned* a, const unsigned* b) {
    asm volatile(
        "mma.sync.aligned.m16n8k8.row.col.f32.tf32.tf32.f32 "
        "{%0,%1,%2,%3}, {%4,%5,%6,%7}, {%8,%9}, {%0,%1,%2,%3};"
        : "+f"(c[0]), "+f"(c[1]), "+f"(c[2]), "+f"(c[3])
        : "r"(a[0]), "r"(a[1]), "r"(a[2]), "r"(a[3]),
          "r"(b[0]), "r"(b[1]));
}

__device__ __forceinline__ float block_reduce_sum(float v) {
    __shared__ float sb[33];
    __syncthreads();
    int lane = threadIdx.x & 31, wid = threadIdx.x >> 5;
    #pragma unroll
    for (int o = 16; o > 0; o >>= 1) v += __shfl_down_sync(0xffffffffu, v, o);
    if (lane == 0) sb[wid] = v;
    __syncthreads();
    if (threadIdx.x == 0) {
        float s = 0.f;
        int nw = blockDim.x >> 5;
        for (int i = 0; i < nw; i++) s += sb[i];
        sb[32] = s;
    }
    __syncthreads();
    return sb[32];
}

// ---------------- embedding ----------------
__global__ __launch_bounds__(128) void embed_kernel(
    const int* __restrict__ ids, const float* __restrict__ tok,
    const float* __restrict__ pos)
{
    int t = blockIdx.x;
    int tid = threadIdx.x;
    if (t == 0 && tid == 0) g_aux[0] = 0.f;
    int id = ids[t];
    int s  = t & (SEQ - 1);
    float4 a = ((const float4*)(tok + (size_t)id * DIM))[tid];
    float4 b = ((const float4*)(pos + (size_t)s  * DIM))[tid];
    float4 o; o.x = a.x + b.x; o.y = a.y + b.y; o.z = a.z + b.z; o.w = a.w + b.w;
    ((float4*)(g_x + (size_t)t * DIM))[tid] = o;
}

// ---------------- rmsnorm ----------------
__global__ __launch_bounds__(128) void rmsnorm_kernel(
    const float* __restrict__ X, const float* __restrict__ w, float* __restrict__ Y)
{
    int t = blockIdx.x;
    int tid = threadIdx.x;
    float4 v = ((const float4*)(X + (size_t)t * DIM))[tid];
    float ss = v.x*v.x + v.y*v.y + v.z*v.z + v.w*v.w;
    ss = block_reduce_sum(ss);
    float scale = rsqrtf(ss * (1.0f / DIM) + 1e-6f);
    float4 wv = ((const float4*)w)[tid];
    float4 o;
    o.x = v.x * scale * wv.x;
    o.y = v.y * scale * wv.y;
    o.z = v.z * scale * wv.z;
    o.w = v.w * scale * wv.w;
    ((float4*)(Y + (size_t)t * DIM))[tid] = o;
}

// ---------------- generic SGEMM 128x128x16 (FFMA, fp32-exact) ------------
// IDENTICAL arithmetic to the Round-2/3/4 passing kernel; only change is
// register prefetch of the next K-slab (scheduling, not rounding).
// MODE 0: C = acc + bias (bias nullable)
// MODE 1: C += acc + bias
// MODE 2: A gathered via rowmap (pad->0), weights via tileexp, C = gelu(acc+bias)
// MODE 3: weights via tileexp, C[rowmap[gm]] += topw*(acc+bias)
template <int MODE>
__global__ void __launch_bounds__(256) sgemm_k(
    int N, int K,
    const float* __restrict__ A,
    const float* __restrict__ B,
    const float* __restrict__ bias,
    float* __restrict__ C,
    const int* __restrict__ rowmap,
    const int* __restrict__ tileexp,
    long bStride, long biasStride,
    const float* __restrict__ topw)
{
    const int bx = blockIdx.x;
    const int by = blockIdx.y;
    if (MODE == 2 || MODE == 3) {
        int e = tileexp[by];
        if (e < 0) return;
        B    += (long)e * bStride;
        bias += (long)e * biasStride;
    }
    __shared__ float As[16][128];
    __shared__ float Bs[16][128];
    const int tid  = threadIdx.x;
    const int arow = tid >> 2;
    const int acol = (tid & 3) << 2;
    const int brow = tid >> 5;
    const int bcol = (tid & 31) << 2;

    const float* ap0; const float* ap1;
    {
        int r0 = by * 128 + arow;
        int r1 = r0 + 64;
        if (MODE == 2) {
            int t0 = rowmap[r0];
            int t1 = rowmap[r1];
            ap0 = (t0 >= 0) ? A + (long)t0 * K : nullptr;
            ap1 = (t1 >= 0) ? A + (long)t1 * K : nullptr;
        } else {
            ap0 = A + (long)r0 * K;
            ap1 = A + (long)r1 * K;
        }
    }
    const float* bp = B + (long)bx * 128 + bcol;

    float acc[8][8];
    #pragma unroll
    for (int i = 0; i < 8; i++)
        #pragma unroll
        for (int j = 0; j < 8; j++) acc[i][j] = 0.f;

    const int tr = (tid >> 4) << 3;
    const int tc = (tid & 15) << 3;

    // initial prefetch (k0 = 0)
    float4 a0 = ap0 ? *(const float4*)(ap0 + acol) : make_float4(0.f,0.f,0.f,0.f);
    float4 a1 = ap1 ? *(const float4*)(ap1 + acol) : make_float4(0.f,0.f,0.f,0.f);
    float4 b0 = *(const float4*)(bp + (long)brow * N);
    float4 b1 = *(const float4*)(bp + (long)(brow + 8) * N);

    for (int k0 = 0; k0 < K; k0 += 16) {
        // stage current slab
        As[acol+0][arow]    = a0.x;
        As[acol+1][arow]    = a0.y;
        As[acol+2][arow]    = a0.z;
        As[acol+3][arow]    = a0.w;
        As[acol+0][arow+64] = a1.x;
        As[acol+1][arow+64] = a1.y;
        As[acol+2][arow+64] = a1.z;
        As[acol+3][arow+64] = a1.w;
        *(float4*)&Bs[brow][bcol]     = b0;
        *(float4*)&Bs[brow + 8][bcol] = b1;
        __syncthreads();

        // prefetch next slab: LDG latency hides under the FMA block below
        if (k0 + 16 < K) {
            a0 = ap0 ? *(const float4*)(ap0 + k0 + 16 + acol) : make_float4(0.f,0.f,0.f,0.f);
            a1 = ap1 ? *(const float4*)(ap1 + k0 + 16 + acol) : make_float4(0.f,0.f,0.f,0.f);
            b0 = *(const float4*)(bp + (long)(k0 + 16 + brow) * N);
            b1 = *(const float4*)(bp + (long)(k0 + 16 + brow + 8) * N);
        }

        #pragma unroll
        for (int k = 0; k < 16; k++) {
            float4 m0 = *(const float4*)&As[k][tr];
            float4 m1 = *(const float4*)&As[k][tr + 4];
            float4 n0 = *(const float4*)&Bs[k][tc];
            float4 n1 = *(const float4*)&Bs[k][tc + 4];
            float rm[8] = {m0.x, m0.y, m0.z, m0.w, m1.x, m1.y, m1.z, m1.w};
            float rn[8] = {n0.x, n0.y, n0.z, n0.w, n1.x, n1.y, n1.z, n1.w};
            #pragma unroll
            for (int i = 0; i < 8; i++)
                #pragma unroll
                for (int j = 0; j < 8; j++)
                    acc[i][j] += rm[i] * rn[j];
        }
        __syncthreads();
    }

    #pragma unroll
    for (int i = 0; i < 8; i++) {
        int gm = by * 128 + tr + i;
        int gn = bx * 128 + tc;
        if (MODE == 0) {
            float* cp = C + (long)gm * N + gn;
            #pragma unroll
            for (int j = 0; j < 8; j++)
                cp[j] = acc[i][j] + (bias ? bias[gn + j] : 0.f);
        } else if (MODE == 1) {
            float* cp = C + (long)gm * N + gn;
            #pragma unroll
            for (int j = 0; j < 8; j++)
                cp[j] = cp[j] + acc[i][j] + bias[gn + j];
        } else if (MODE == 2) {
            float* cp = C + (long)gm * N + gn;
            #pragma unroll
            for (int j = 0; j < 8; j++)
                cp[j] = gelu_exact(acc[i][j] + bias[gn + j]);
        } else {
            int t = rowmap[gm];
            if (t >= 0) {
                float w = topw[t];
                float* cp = C + (long)t * N + gn;
                #pragma unroll
                for (int j = 0; j < 8; j++)
                    cp[j] += w * (acc[i][j] + bias[gn + j]);
            }
        }
    }
}

// ---------------- LM head: plain tf32 mma.sync GEMM, register-prefetched ------
// Only the terminal logits use tf32 (noise-safe; Round-4 validated at 2.95e-4).
#define LM_SMEM (2 * 2176 * 4)
__global__ void __launch_bounds__(256) lm_head_tf32_kernel(
    const float* __restrict__ A, const float* __restrict__ B, float* __restrict__ C)
{
    extern __shared__ unsigned dsm_u[];
    unsigned* As = dsm_u;            // [16][136] k-major (transposed A)
    unsigned* Bs = dsm_u + 2176;     // [16][136]
    const int N = VOC, K = DIM;
    const int bx = blockIdx.x;
    const int by = blockIdx.y;
    const int tid  = threadIdx.x;
    const int wid  = tid >> 5;
    const int lane = tid & 31;
    const int WM = (wid >> 2) * 64;
    const int WN = (wid & 3) * 32;
    const int g  = lane >> 2;
    const int tg = lane & 3;

    const int arow = tid >> 2;
    const int acol = (tid & 3) << 2;
    const int brow = tid >> 5;
    const int bcol = (tid & 31) << 2;

    const float* ap0 = A + (long)(by * 128 + arow) * K;
    const float* ap1 = ap0 + (long)64 * K;
    const float* bp  = B + (long)bx * 128 + bcol;

    float acc[4][4][4];
    #pragma unroll
    for (int mt = 0; mt < 4; mt++)
        #pragma unroll
        for (int nt = 0; nt < 4; nt++)
            #pragma unroll
            for (int r = 0; r < 4; r++) acc[mt][nt][r] = 0.f;

    float4 ra0 = *(const float4*)(ap0 + acol);
    float4 ra1 = *(const float4*)(ap1 + acol);
    float4 rb0 = *(const float4*)(bp + (long)brow * N);
    float4 rb1 = *(const float4*)(bp + (long)(brow + 8) * N);

    for (int k0 = 0; k0 < K; k0 += 16) {
        As[(acol+0) * 136 + arow]      = f2tf(ra0.x);
        As[(acol+1) * 136 + arow]      = f2tf(ra0.y);
        As[(acol+2) * 136 + arow]      = f2tf(ra0.z);
        As[(acol+3) * 136 + arow]      = f2tf(ra0.w);
        As[(acol+0) * 136 + arow + 64] = f2tf(ra1.x);
        As[(acol+1) * 136 + arow + 64] = f2tf(ra1.y);
        As[(acol+2) * 136 + arow + 64] = f2tf(ra1.z);
        As[(acol+3) * 136 + arow + 64] = f2tf(ra1.w);
        {
            uint4 v0 = make_uint4(f2tf(rb0.x), f2tf(rb0.y), f2tf(rb0.z), f2tf(rb0.w));
            uint4 v1 = make_uint4(f2tf(rb1.x), f2tf(rb1.y), f2tf(rb1.z), f2tf(rb1.w));
            *(uint4*)&Bs[brow * 136 + bcol]       = v0;
            *(uint4*)&Bs[(brow + 8) * 136 + bcol] = v1;
        }
        __syncthreads();

        if (k0 + 16 < K) {
            ra0 = *(const float4*)(ap0 + k0 + 16 + acol);
            ra1 = *(const float4*)(ap1 + k0 + 16 + acol);
            rb0 = *(const float4*)(bp + (long)(k0 + 16 + brow) * N);
            rb1 = *(const float4*)(bp + (long)(k0 + 16 + brow + 8) * N);
        }

        #pragma unroll
        for (int kk = 0; kk < 16; kk += 8) {
            unsigned bfr[4][2];
            #pragma unroll
            for (int nt = 0; nt < 4; nt++) {
                int n0 = WN + nt * 8;
                bfr[nt][0] = Bs[(kk + tg) * 136 + n0 + g];
                bfr[nt][1] = Bs[(kk + 4 + tg) * 136 + n0 + g];
            }
            #pragma unroll
            for (int mt = 0; mt < 4; mt++) {
                int m0 = WM + mt * 16;
                unsigned afr[4];
                afr[0] = As[(kk + tg) * 136 + m0 + g];
                afr[1] = As[(kk + tg) * 136 + m0 + 8 + g];
                afr[2] = As[(kk + 4 + tg) * 136 + m0 + g];
                afr[3] = As[(kk + 4 + tg) * 136 + m0 + 8 + g];
                #pragma unroll
                for (int nt = 0; nt < 4; nt++)
                    mma_tf32(acc[mt][nt], afr, bfr[nt]);
            }
        }
        __syncthreads();
    }

    #pragma unroll
    for (int mt = 0; mt < 4; mt++) {
        int r0 = by * 128 + WM + mt * 16 + g;
        #pragma unroll
        for (int nt = 0; nt < 4; nt++) {
            int c0 = bx * 128 + WN + nt * 8 + tg * 2;
            *(float2*)(C + (long)r0 * N + c0)       = make_float2(acc[mt][nt][0], acc[mt][nt][1]);
            *(float2*)(C + (long)(r0 + 8) * N + c0) = make_float2(acc[mt][nt][2], acc[mt][nt][3]);
        }
    }
}

// ---------------- fused flash attention (work-paired) ----------------
__device__ __forceinline__ int fa_swz(int d, int r) {
    return d * 64 + ((((r >> 2) ^ (d & 15)) << 2) | (r & 3));
}
__device__ __forceinline__ float4 fa_ld4(const float* buf, int d, int r4) {
    return *(const float4*)(buf + d * 64 + ((r4 ^ (d & 15)) << 2));
}

__global__ void __launch_bounds__(256) flash_attn_kernel()
{
    __shared__ float Qt[64*64];
    __shared__ float KPt[64*64];
    __shared__ float Vs[64*64];
    const int bh = blockIdx.y;
    const int b = bh >> 3, h = bh & 7;
    const int tid = threadIdx.x;
    const int tr = (tid >> 4) << 2;
    const int tc = (tid & 15) << 2;
    const int r4q = tr >> 2;
    const int c4  = tc >> 2;

    for (int pass = 0; pass < 2; pass++) {
        const int qt = pass ? (15 - (int)blockIdx.x) : (int)blockIdx.x;
        const float* Qbase = g_qkv + ((size_t)(b * SEQ + qt * 64)) * 1536 + h * DHD;
        #pragma unroll
        for (int rep = 0; rep < 4; rep++) {
            int idx = rep * 256 + tid;
            int row = idx >> 4;
            int d4  = (idx & 15) << 2;
            float4 v = *(const float4*)(Qbase + (size_t)row * 1536 + d4);
            Qt[fa_swz(d4+0, row)] = v.x;
            Qt[fa_swz(d4+1, row)] = v.y;
            Qt[fa_swz(d4+2, row)] = v.z;
            Qt[fa_swz(d4+3, row)] = v.w;
        }

        float m[4], l[4], acc[4][4];
        #pragma unroll
        for (int i = 0; i < 4; i++) {
            m[i] = -1e30f; l[i] = 0.f;
            #pragma unroll
            for (int j = 0; j < 4; j++) acc[i][j] = 0.f;
        }

        for (int kt = 0; kt <= qt; kt++) {
            __syncthreads();
            const float* Kbase = g_qkv + ((size_t)(b * SEQ + kt * 64)) * 1536 + DIM + h * DHD;
            const float* Vbase = Kbase + DIM;
            #pragma unroll
            for (int rep = 0; rep < 4; rep++) {
                int idx = rep * 256 + tid;
                int row = idx >> 4;
                int d4  = (idx & 15) << 2;
                float4 kv = *(const float4*)(Kbase + (size_t)row * 1536 + d4);
                KPt[fa_swz(d4+0, row)] = kv.x;
                KPt[fa_swz(d4+1, row)] = kv.y;
                KPt[fa_swz(d4+2, row)] = kv.z;
                KPt[fa_swz(d4+3, row)] = kv.w;
                float4 vv = *(const float4*)(Vbase + (size_t)row * 1536 + d4);
                *(float4*)(Vs + row * 64 + d4) = vv;
            }
            __syncthreads();

            float s[4][4];
            #pragma unroll
            for (int i = 0; i < 4; i++)
                #pragma unroll
                for (int j = 0; j < 4; j++) s[i][j] = 0.f;
            #pragma unroll 8
            for (int d = 0; d < DHD; d++) {
                float4 qv = fa_ld4(Qt,  d, r4q);
                float4 kv = fa_ld4(KPt, d, c4);
                float rq[4] = {qv.x, qv.y, qv.z, qv.w};
                float rk[4] = {kv.x, kv.y, kv.z, kv.w};
                #pragma unroll
                for (int i = 0; i < 4; i++)
                    #pragma unroll
                    for (int j = 0; j < 4; j++)
                        s[i][j] += rq[i] * rk[j];
            }

            #pragma unroll
            for (int i = 0; i < 4; i++)
                #pragma unroll
                for (int j = 0; j < 4; j++) {
                    s[i][j] *= 0.125f;
                    if (kt == qt && (tc + j) > (tr + i)) s[i][j] = -1e30f;
                }

            float tm[4];
            #pragma unroll
            for (int i = 0; i < 4; i++) {
                tm[i] = fmaxf(fmaxf(s[i][0], s[i][1]), fmaxf(s[i][2], s[i][3]));
                #pragma unroll
                for (int o = 8; o > 0; o >>= 1)
                    tm[i] = fmaxf(tm[i], __shfl_xor_sync(0xffffffffu, tm[i], o, 16));
            }
            #pragma unroll
            for (int i = 0; i < 4; i++) {
                float mn  = fmaxf(m[i], tm[i]);
                float fac = expf(m[i] - mn);
                m[i] = mn;
                l[i] *= fac;
                #pragma unroll
                for (int j = 0; j < 4; j++) acc[i][j] *= fac;
                float rs = 0.f;
                #pragma unroll
                for (int j = 0; j < 4; j++) {
                    float p = expf(s[i][j] - mn);
                    s[i][j] = p;
                    rs += p;
                }
                #pragma unroll
                for (int o = 8; o > 0; o >>= 1)
                    rs += __shfl_xor_sync(0xffffffffu, rs, o, 16);
                l[i] += rs;
            }

            __syncthreads();
            #pragma unroll
            for (int j = 0; j < 4; j++) {
                int d = tc + j;
                *(float4*)(KPt + d * 64 + ((r4q ^ (d & 15)) << 2)) =
                    make_float4(s[0][j], s[1][j], s[2][j], s[3][j]);
            }
            __syncthreads();

            #pragma unroll 8
            for (int j2 = 0; j2 < 64; j2++) {
                float4 pv = fa_ld4(KPt, j2, r4q);
                float4 vv = *(const float4*)(Vs + j2 * 64 + tc);
                float rp[4] = {pv.x, pv.y, pv.z, pv.w};
                #pragma unroll
                for (int i = 0; i < 4; i++) {
                    acc[i][0] += rp[i] * vv.x;
                    acc[i][1] += rp[i] * vv.y;
                    acc[i][2] += rp[i] * vv.z;
                    acc[i][3] += rp[i] * vv.w;
                }
            }
        }

        #pragma unroll
        for (int i = 0; i < 4; i++) {
            float inv = 1.0f / l[i];
            int q = qt * 64 + tr + i;
            float4 o = make_float4(acc[i][0]*inv, acc[i][1]*inv, acc[i][2]*inv, acc[i][3]*inv);
            *(float4*)(g_o + ((size_t)(b * SEQ + q)) * DIM + h * DHD + tc) = o;
        }
        __syncthreads();
    }
}

// ---------------- router ----------------
__global__ __launch_bounds__(32) void zero_router_kernel()
{
    if (threadIdx.x < NEXP) g_cnt[threadIdx.x] = 0;
}

__global__ __launch_bounds__(128) void router_kernel(
    const float* __restrict__ rW, const float* __restrict__ rb,
    float* __restrict__ rl_out)
{
    int t = blockIdx.x;
    int tid = threadIdx.x;
    float acc[NEXP];
    #pragma unroll
    for (int e = 0; e < NEXP; e++) acc[e] = 0.f;
    for (int k = tid; k < DIM; k += 128) {
        float hv = g_h[(size_t)t * DIM + k];
        const float* r = rW + (size_t)k * NEXP;
        float4 r0 = *(const float4*)(r);
        float4 r1 = *(const float4*)(r + 4);
        acc[0] += hv * r0.x; acc[1] += hv * r0.y; acc[2] += hv * r0.z; acc[3] += hv * r0.w;
        acc[4] += hv * r1.x; acc[5] += hv * r1.y; acc[6] += hv * r1.z; acc[7] += hv * r1.w;
    }
    __shared__ float red[4][NEXP];
    int lane = tid & 31, w = tid >> 5;
    #pragma unroll
    for (int e = 0; e < NEXP; e++)
        #pragma unroll
        for (int o = 16; o > 0; o >>= 1)
            acc[e] += __shfl_down_sync(0xffffffffu, acc[e], o);
    if (lane == 0)
        #pragma unroll
        for (int e = 0; e < NEXP; e++) red[w][e] = acc[e];
    __syncthreads();
    if (tid == 0) {
        float rl[NEXP], p[NEXP];
        #pragma unroll
        for (int e = 0; e < NEXP; e++)
            rl[e] = red[0][e] + red[1][e] + red[2][e] + red[3][e] + rb[e];
        #pragma unroll
        for (int e = 0; e < NEXP; e++) rl_out[(size_t)t * NEXP + e] = rl[e];
        float m = rl[0];
        #pragma unroll
        for (int e = 1; e < NEXP; e++) m = fmaxf(m, rl[e]);
        float s = 0.f;
        #pragma unroll
        for (int e = 0; e < NEXP; e++) { p[e] = expf(rl[e] - m); s += p[e]; }
        float inv = 1.0f / s;
        float best = -1.f; int bi = 0;
        #pragma unroll
        for (int e = 0; e < NEXP; e++) {
            p[e] *= inv;
            g_pe[(size_t)t * NEXP + e] = p[e];
            if (p[e] > best) { best = p[e]; bi = e; }
        }
        g_topi[t] = bi;
        g_topw[t] = best;
        atomicAdd(&g_cnt[bi], 1);
    }
}

__global__ __launch_bounds__(256) void expert_sum_kernel()
{
    int e = blockIdx.x;
    float s = 0.f;
    for (int t = threadIdx.x; t < TKN; t += blockDim.x)
        s += g_pe[(size_t)t * NEXP + e];
    s = block_reduce_sum(s);
    if (threadIdx.x == 0) g_sp[e] = s;
}

__global__ __launch_bounds__(128) void moe_setup_kernel()
{
    int tid = threadIdx.x;
    for (int i = tid; i < MAXROWS; i += blockDim.x) g_perm[i] = -1;
    if (tid < NEXP) g_cursor[tid] = 0;
    __syncthreads();
    if (tid == 0) {
        int off = 0, tile = 0;
        float aux = 0.f;
        for (int e = 0; e < NEXP; e++) {
            g_padoff[e] = off;
            int c = g_cnt[e];
            aux += (float)c * g_sp[e];
            int nt = (c + 127) >> 7;
            for (int k = 0; k < nt; k++) g_tileexp[tile++] = e;
            off += nt << 7;
        }
        for (; tile < MAXTILES; tile++) g_tileexp[tile] = -1;
        g_aux[0] += (float)NEXP * aux / ((float)TKN * (float)TKN);
    }
}

__global__ __launch_bounds__(128) void scatter_kernel()
{
    int t = blockIdx.x * blockDim.x + threadIdx.x;
    if (t >= TKN) return;
    int e = g_topi[t];
    int pos = atomicAdd(&g_cursor[e], 1);
    g_perm[g_padoff[e] + pos] = t;
}

__global__ void write_aux_kernel(float* __restrict__ out)
{
    out[0] = g_aux[0];
}

// ---------------- launch ----------------
extern "C" void kernel_launch(void* const* d_in, const int* in_sizes, int n_in,
                              void* d_out, int out_size)
{
    const int*   ids  = (const int*)  d_in[0];
    const float* tok  = (const float*)d_in[1];
    const float* pos  = (const float*)d_in[2];
    const float* Wqkv = (const float*)d_in[3];
    const float* bqkv = (const float*)d_in[4];
    const float* Wo   = (const float*)d_in[5];
    const float* bo   = (const float*)d_in[6];
    const float* rW   = (const float*)d_in[7];
    const float* rb   = (const float*)d_in[8];
    const float* eW1  = (const float*)d_in[9];
    const float* eb1  = (const float*)d_in[10];
    const float* eW2  = (const float*)d_in[11];
    const float* eb2  = (const float*)d_in[12];
    const float* n1w  = (const float*)d_in[13];
    const float* n2w  = (const float*)d_in[14];
    const float* noww = (const float*)d_in[15];
    const float* lmW  = (const float*)d_in[16];
    float* out = (float*)d_out;

    void *px, *ph, *pqkv, *po, *phid, *pperm, *ptile, *ptopw;
    cudaGetSymbolAddress(&px,   g_x);
    cudaGetSymbolAddress(&ph,   g_h);
    cudaGetSymbolAddress(&pqkv, g_qkv);
    cudaGetSymbolAddress(&po,   g_o);
    cudaGetSymbolAddress(&phid, g_hid);
    cudaGetSymbolAddress(&pperm, g_perm);
    cudaGetSymbolAddress(&ptile, g_tileexp);
    cudaGetSymbolAddress(&ptopw, g_topw);
    float* x   = (float*)px;
    float* h   = (float*)ph;
    float* qkv = (float*)pqkv;
    float* o   = (float*)po;
    float* hid = (float*)phid;

    embed_kernel<<<TKN, 128>>>(ids, tok, pos);

    for (int l = 0; l < NLAYER; l++) {
        // attention block
        rmsnorm_kernel<<<TKN, 128>>>(x, n1w + (size_t)l * DIM, h);
        sgemm_k<0><<<dim3(12, 16), 256>>>(3 * DIM, DIM,
            h, Wqkv + (size_t)l * DIM * 3 * DIM, bqkv + (size_t)l * 3 * DIM,
            qkv, nullptr, nullptr, 0, 0, nullptr);
        flash_attn_kernel<<<dim3(8, BATCH * NH), 256>>>();
        sgemm_k<1><<<dim3(4, 16), 256>>>(DIM, DIM,
            o, Wo + (size_t)l * DIM * DIM, bo + (size_t)l * DIM,
            x, nullptr, nullptr, 0, 0, nullptr);

        // MoE block
        rmsnorm_kernel<<<TKN, 128>>>(x, n2w + (size_t)l * DIM, h);
        zero_router_kernel<<<1, 32>>>();
        router_kernel<<<TKN, 128>>>(rW + (size_t)l * DIM * NEXP,
                                    rb + (size_t)l * NEXP,
                                    out + RL_OFF + (size_t)l * TKN * NEXP);
        expert_sum_kernel<<<NEXP, 256>>>();
        moe_setup_kernel<<<1, 128>>>();
        scatter_kernel<<<16, 128>>>();

        sgemm_k<2><<<dim3(16, MAXTILES), 256>>>(FFD, DIM,
            h, eW1 + (size_t)l * NEXP * DIM * FFD, eb1 + (size_t)l * NEXP * FFD,
            hid, (const int*)pperm, (const int*)ptile,
            (long)DIM * FFD, (long)FFD, nullptr);
        sgemm_k<3><<<dim3(4, MAXTILES), 256>>>(DIM, FFD,
            hid, eW2 + (size_t)l * NEXP * FFD * DIM, eb2 + (size_t)l * NEXP * DIM,
            x, (const int*)pperm, (const int*)ptile,
            (long)FFD * DIM, (long)DIM, (const float*)ptopw);
    }

    // final norm + LM head (tf32: logits are terminal)
    rmsnorm_kernel<<<TKN, 128>>>(x, noww, h);
    lm_head_tf32_kernel<<<dim3(VOC / 128, 16), 256, LM_SMEM>>>(h, lmW, out);
    write_aux_kernel<<<1, 1>>>(out + AUX_OFF);
}